// round 12
// baseline (speedup 1.0000x reference)
#include <cuda_runtime.h>
#include <cuda_fp16.h>
#include <math.h>
#include <stdint.h>

#define N_NODES 50000
#define N_EDGES 800000
#define NEG_SLOPE 0.2f

// ---------------- scratch (device globals; no allocation allowed) ----------------
__device__ float  g_ft1[N_NODES * 256];
__device__ float  g_h1 [N_NODES * 256];
__device__ float  g_el1[N_NODES * 4];
__device__ float  g_er1[N_NODES * 4];
__device__ float  g_ft2[N_NODES * 128];
__device__ float  g_el2p[2 * N_NODES];
__device__ float  g_er2p[2 * N_NODES];
__device__ int    g_cnt[N_NODES];
__device__ int    g_rowptr[N_NODES + 1];
__device__ int    g_colsrc[N_EDGES];
__device__ __half g_wt1h[256 * 256];   // W1^T hi fp16 [n][k]
__device__ __half g_wt1l[256 * 256];   // W1^T lo fp16
__device__ __half g_wt2h[128 * 256];   // W2^T hi
__device__ __half g_wt2l[128 * 256];   // W2^T lo

// ---------------- helpers ----------------
__device__ __forceinline__ uint32_t smem_u32(const void* p) {
    uint32_t a;
    asm("{ .reg .u64 t; cvta.to.shared.u64 t, %1; cvt.u32.u64 %0, t; }" : "=r"(a) : "l"(p));
    return a;
}

#define CP_ASYNC16(sa, gp) \
    asm volatile("cp.async.cg.shared.global [%0], [%1], 16;" :: "r"(sa), "l"(gp) : "memory")
#define CP_ASYNC16_Z(sa, gp, sz) \
    asm volatile("cp.async.cg.shared.global [%0], [%1], 16, %2;" :: "r"(sa), "l"(gp), "r"(sz) : "memory")
#define CP_COMMIT()  asm volatile("cp.async.commit_group;" ::: "memory")
#define CP_WAIT(n)   asm volatile("cp.async.wait_group %0;" :: "n"(n) : "memory")

#define MMA_F16(d, a0, a1, a2, a3, b0, b1)                                    \
    asm volatile("mma.sync.aligned.m16n8k16.row.col.f32.f16.f16.f32 "         \
                 "{%0,%1,%2,%3}, {%4,%5,%6,%7}, {%8,%9}, {%0,%1,%2,%3};"      \
                 : "+f"(d[0]), "+f"(d[1]), "+f"(d[2]), "+f"(d[3])             \
                 : "r"(a0), "r"(a1), "r"(a2), "r"(a3), "r"(b0), "r"(b1))

// split a float2 into packed fp16 hi + fp16 residual lo
__device__ __forceinline__ void split2(float2 x, uint32_t& h, uint32_t& l) {
    __half2 hh = __floats2half2_rn(x.x, x.y);
    float2 hf = __half22float2(hh);
    __half2 ll = __floats2half2_rn(x.x - hf.x, x.y - hf.y);
    h = *reinterpret_cast<uint32_t*>(&hh);
    l = *reinterpret_cast<uint32_t*>(&ll);
}

// ---------------- small utils ----------------
__global__ void count_dst_kernel(const int* __restrict__ dst, int* __restrict__ cnt, int E) {
    for (int e = blockIdx.x * blockDim.x + threadIdx.x; e < E; e += gridDim.x * blockDim.x)
        atomicAdd(&cnt[dst[e]], 1);
}

// transpose + fp16 hi/lo split of both weight matrices; also zeroes cnt[]
__global__ void transpose_split_kernel(const float* __restrict__ W1, const float* __restrict__ W2,
                                       __half* __restrict__ t1h, __half* __restrict__ t1l,
                                       __half* __restrict__ t2h, __half* __restrict__ t2l,
                                       int* __restrict__ cnt) {
    int t = blockIdx.x * blockDim.x + threadIdx.x;
    if (t < N_NODES) cnt[t] = 0;
    if (t < 65536) {
        int k = t & 255, n = t >> 8;
        float v = W1[k * 256 + n];
        __half h = __float2half_rn(v);
        t1h[n * 256 + k] = h;
        t1l[n * 256 + k] = __float2half_rn(v - __half2float(h));
    } else if (t < 98304) {
        int u = t - 65536;
        int k = u & 255, n = u >> 8;
        float v = W2[k * 128 + n];
        __half h = __float2half_rn(v);
        t2h[n * 256 + k] = h;
        t2l[n * 256 + k] = __float2half_rn(v - __half2float(h));
    }
}

// single-block exclusive scan
__global__ void scan_kernel(const int* __restrict__ cnt, int* __restrict__ rowptr, int n) {
    __shared__ int warp_sums[32];
    __shared__ int s_carry;
    int tid = threadIdx.x;
    if (tid == 0) { s_carry = 0; rowptr[0] = 0; }
    __syncthreads();
    for (int base = 0; base < n; base += 1024) {
        int idx = base + tid;
        int v = (idx < n) ? cnt[idx] : 0;
        int lane = tid & 31, warp = tid >> 5;
        int x = v;
        #pragma unroll
        for (int off = 1; off < 32; off <<= 1) {
            int y = __shfl_up_sync(0xffffffffu, x, off);
            if (lane >= off) x += y;
        }
        if (lane == 31) warp_sums[warp] = x;
        __syncthreads();
        if (warp == 0) {
            int s = warp_sums[lane];
            #pragma unroll
            for (int off = 1; off < 32; off <<= 1) {
                int y = __shfl_up_sync(0xffffffffu, s, off);
                if (lane >= off) s += y;
            }
            warp_sums[lane] = s;
        }
        __syncthreads();
        int warp_off = (warp > 0) ? warp_sums[warp - 1] : 0;
        int incl = x + warp_off + s_carry;
        if (idx < n) rowptr[idx + 1] = incl;
        __syncthreads();
        if (tid == 1023) s_carry = incl;
        __syncthreads();
    }
}

__global__ void scatter_kernel(const int* __restrict__ src, const int* __restrict__ dst,
                               const int* __restrict__ rowptr, int* __restrict__ cnt,
                               int* __restrict__ colsrc, int E) {
    for (int e = blockIdx.x * blockDim.x + threadIdx.x; e < E; e += gridDim.x * blockDim.x) {
        int d = dst[e];
        int pos = atomicSub(&cnt[d], 1);
        colsrc[rowptr[d] + pos - 1] = src[e];
    }
}

// ---------------- fp16 split-MMA GEMM (cp.async double-buffered) + fused el/er ----------------
// 8x1 warp grid: warp owns 16 full rows (16x64 warp tile).
// ASTR=44: row bank step 12g mod 32 -> all 8 fragment rows in distinct banks (conflict-free),
// and (44r + 4k)*4B stays 16B-aligned for cp.async.
template <int HEADS>
__global__ __launch_bounds__(256, 3) void mma_gemm_f16_kernel(
    const float* __restrict__ A,
    const __half* __restrict__ Bth, const __half* __restrict__ Btl,
    float* __restrict__ C,
    const float* __restrict__ attn_l, const float* __restrict__ attn_r,
    float* __restrict__ el, float* __restrict__ er,
    int M, int Nc)
{
    const int BM = 128, BN = 64, BK = 32, K = 256;
    const int ASTR = 44;    // f32 per A row (conflict-free fragment LDS)
    const int ASTR2 = ASTR / 2;
    const int BSTR2 = 20;   // half2 per B row
    extern __shared__ float sm[];
    float*   As  = sm;                                    // [2][BM][44] f32
    __half2* Bh2 = (__half2*)(As + 2 * BM * ASTR);        // [2][BN][20] half2 hi
    __half2* Bl2 = Bh2 + 2 * BN * BSTR2;                  // [2][BN][20] half2 lo

    uint32_t as_b = smem_u32(As);
    uint32_t bh_b = smem_u32(Bh2);
    uint32_t bl_b = smem_u32(Bl2);

    int tid = threadIdx.x, lane = tid & 31, warp = tid >> 5;
    int blockRow = blockIdx.y * BM;
    int blockCol = blockIdx.x * BN;
    int g = lane >> 2, q = lane & 3;

    float acc[8][4];
    #pragma unroll
    for (int j = 0; j < 8; j++)
        #pragma unroll
        for (int c = 0; c < 4; c++) acc[j][c] = 0.f;

    auto load_tile = [&](int t) {
        int buf = t & 1, k0 = t * BK;
        #pragma unroll
        for (int l = 0; l < 4; l++) {
            int c = tid + l * 256;
            int r = c >> 3, kq = (c & 7) * 4;
            const float* gp = A + (size_t)(blockRow + r) * K + k0 + kq;
            uint32_t sa = as_b + (uint32_t)(((buf * BM + r) * ASTR + kq) * 4);
            uint32_t sz = (blockRow + r < M) ? 16u : 0u;
            CP_ASYNC16_Z(sa, gp, sz);
        }
        {
            int n = tid >> 2, ch = tid & 3;
            size_t go = (size_t)(blockCol + n) * K + k0 + ch * 8;
            uint32_t so = (uint32_t)(((buf * BN + n) * BSTR2 + ch * 4) * 4);
            CP_ASYNC16(bh_b + so, Bth + go);
            CP_ASYNC16(bl_b + so, Btl + go);
        }
        CP_COMMIT();
    };

    load_tile(0);

    #pragma unroll 1
    for (int t = 0; t < K / BK; t++) {
        if (t < K / BK - 1) {
            load_tile(t + 1);
            CP_WAIT(1);
        } else {
            CP_WAIT(0);
        }
        __syncthreads();

        int buf = t & 1;
        const float2*  Af2 = (const float2*)(As + buf * BM * ASTR);
        const __half2* Bhb = Bh2 + buf * BN * BSTR2;
        const __half2* Blb = Bl2 + buf * BN * BSTR2;

        #pragma unroll
        for (int ks = 0; ks < 2; ks++) {
            int kof = ks * 8;
            int r0 = warp * 16 + g;
            uint32_t ah[4], al[4];
            float2 x00 = Af2[(r0    ) * ASTR2 + kof + q];
            float2 x10 = Af2[(r0 + 8) * ASTR2 + kof + q];
            float2 x01 = Af2[(r0    ) * ASTR2 + kof + q + 4];
            float2 x11 = Af2[(r0 + 8) * ASTR2 + kof + q + 4];
            split2(x00, ah[0], al[0]);
            split2(x10, ah[1], al[1]);
            split2(x01, ah[2], al[2]);
            split2(x11, ah[3], al[3]);
            #pragma unroll
            for (int j = 0; j < 8; j++) {
                int nb = j * 8 + g;
                uint32_t b0h = *reinterpret_cast<const uint32_t*>(&Bhb[nb * BSTR2 + kof + q]);
                uint32_t b1h = *reinterpret_cast<const uint32_t*>(&Bhb[nb * BSTR2 + kof + q + 4]);
                uint32_t b0l = *reinterpret_cast<const uint32_t*>(&Blb[nb * BSTR2 + kof + q]);
                uint32_t b1l = *reinterpret_cast<const uint32_t*>(&Blb[nb * BSTR2 + kof + q + 4]);
                MMA_F16(acc[j], ah[0], ah[1], ah[2], ah[3], b0h, b1h);
                MMA_F16(acc[j], al[0], al[1], al[2], al[3], b0h, b1h);
                MMA_F16(acc[j], ah[0], ah[1], ah[2], ah[3], b0l, b1l);
            }
        }
        __syncthreads();
    }

    // ---- store C (fp32) ----
    int r0 = blockRow + warp * 16 + g;
    int r1 = r0 + 8;
    #pragma unroll
    for (int j = 0; j < 8; j++) {
        int c = blockCol + j * 8 + q * 2;
        if (r0 < M) *(float2*)(C + (size_t)r0 * Nc + c) = make_float2(acc[j][0], acc[j][1]);
        if (r1 < M) *(float2*)(C + (size_t)r1 * Nc + c) = make_float2(acc[j][2], acc[j][3]);
    }

    // ---- fused el/er epilogue: whole row in one warp -> q-shuffle completes dot ----
    float pl0 = 0.f, pl1 = 0.f, pr0 = 0.f, pr1 = 0.f;
    #pragma unroll
    for (int j = 0; j < 8; j++) {
        int idx = blockCol + j * 8 + q * 2;
        float a0 = __ldg(&attn_l[idx]), a1 = __ldg(&attn_l[idx + 1]);
        float b0 = __ldg(&attn_r[idx]), b1 = __ldg(&attn_r[idx + 1]);
        pl0 += acc[j][0] * a0 + acc[j][1] * a1;
        pl1 += acc[j][2] * a0 + acc[j][3] * a1;
        pr0 += acc[j][0] * b0 + acc[j][1] * b1;
        pr1 += acc[j][2] * b0 + acc[j][3] * b1;
    }
    #pragma unroll
    for (int off = 1; off <= 2; off <<= 1) {
        pl0 += __shfl_xor_sync(0xffffffffu, pl0, off);
        pl1 += __shfl_xor_sync(0xffffffffu, pl1, off);
        pr0 += __shfl_xor_sync(0xffffffffu, pr0, off);
        pr1 += __shfl_xor_sync(0xffffffffu, pr1, off);
    }
    if (q == 0) {
        if (r0 < M) {
            if (HEADS == 1) {
                el[(size_t)blockIdx.x * M + r0] = pl0;
                er[(size_t)blockIdx.x * M + r0] = pr0;
            } else {
                el[(size_t)r0 * HEADS + blockIdx.x] = pl0;
                er[(size_t)r0 * HEADS + blockIdx.x] = pr0;
            }
        }
        if (r1 < M) {
            if (HEADS == 1) {
                el[(size_t)blockIdx.x * M + r1] = pl1;
                er[(size_t)blockIdx.x * M + r1] = pr1;
            } else {
                el[(size_t)r1 * HEADS + blockIdx.x] = pl1;
                er[(size_t)r1 * HEADS + blockIdx.x] = pr1;
            }
        }
    }
}

// ---------------- fused softmax + aggregation ----------------
__device__ __forceinline__ float leaky_exp(float e) {
    e = (e > 0.f) ? e : NEG_SLOPE * e;
    return __expf(e);
}

// layer 1: H=4, D=64, C=256, fp32 features. One warp per node.
__global__ __launch_bounds__(256) void aggregate1_kernel(
    const float* __restrict__ ft, const float* __restrict__ el, const float* __restrict__ er,
    const int* __restrict__ rowptr, const int* __restrict__ colsrc,
    const float* __restrict__ bias, float* __restrict__ out, int Nn)
{
    int warp = threadIdx.x >> 5, lane = threadIdx.x & 31;
    int n = blockIdx.x * 8 + warp;
    if (n >= Nn) return;
    int start = rowptr[n];
    int deg = rowptr[n + 1] - start;

    const bool hlo = (lane < 16);
    float4 er4 = __ldg((const float4*)(er + (size_t)n * 4));
    float erA = hlo ? er4.x : er4.y;
    float erB = hlo ? er4.z : er4.w;

    float4 accA = make_float4(0.f, 0.f, 0.f, 0.f);
    float4 accB = make_float4(0.f, 0.f, 0.f, 0.f);
    float wsumA = 0.f, wsumB = 0.f;
    const float* ftA = ft + lane * 4;
    const float* ftB = ft + 128 + lane * 4;

    int k = 0;
    for (; k + 4 <= deg; k += 4) {
        int s0 = __ldg(&colsrc[start + k + 0]);
        int s1 = __ldg(&colsrc[start + k + 1]);
        int s2 = __ldg(&colsrc[start + k + 2]);
        int s3 = __ldg(&colsrc[start + k + 3]);
        float4 l0 = __ldg((const float4*)(el + (size_t)s0 * 4));
        float4 l1 = __ldg((const float4*)(el + (size_t)s1 * 4));
        float4 l2 = __ldg((const float4*)(el + (size_t)s2 * 4));
        float4 l3 = __ldg((const float4*)(el + (size_t)s3 * 4));
        float4 fA0 = *(const float4*)(ftA + (size_t)s0 * 256);
        float4 fB0 = *(const float4*)(ftB + (size_t)s0 * 256);
        float4 fA1 = *(const float4*)(ftA + (size_t)s1 * 256);
        float4 fB1 = *(const float4*)(ftB + (size_t)s1 * 256);
        float4 fA2 = *(const float4*)(ftA + (size_t)s2 * 256);
        float4 fB2 = *(const float4*)(ftB + (size_t)s2 * 256);
        float4 fA3 = *(const float4*)(ftA + (size_t)s3 * 256);
        float4 fB3 = *(const float4*)(ftB + (size_t)s3 * 256);
        float wA0 = leaky_exp((hlo ? l0.x : l0.y) + erA);
        float wB0 = leaky_exp((hlo ? l0.z : l0.w) + erB);
        float wA1 = leaky_exp((hlo ? l1.x : l1.y) + erA);
        float wB1 = leaky_exp((hlo ? l1.z : l1.w) + erB);
        float wA2 = leaky_exp((hlo ? l2.x : l2.y) + erA);
        float wB2 = leaky_exp((hlo ? l2.z : l2.w) + erB);
        float wA3 = leaky_exp((hlo ? l3.x : l3.y) + erA);
        float wB3 = leaky_exp((hlo ? l3.z : l3.w) + erB);
        accA.x += wA0 * fA0.x + wA1 * fA1.x + wA2 * fA2.x + wA3 * fA3.x;
        accA.y += wA0 * fA0.y + wA1 * fA1.y + wA2 * fA2.y + wA3 * fA3.y;
        accA.z += wA0 * fA0.z + wA1 * fA1.z + wA2 * fA2.z + wA3 * fA3.z;
        accA.w += wA0 * fA0.w + wA1 * fA1.w + wA2 * fA2.w + wA3 * fA3.w;
        accB.x += wB0 * fB0.x + wB1 * fB1.x + wB2 * fB2.x + wB3 * fB3.x;
        accB.y += wB0 * fB0.y + wB1 * fB1.y + wB2 * fB2.y + wB3 * fB3.y;
        accB.z += wB0 * fB0.z + wB1 * fB1.z + wB2 * fB2.z + wB3 * fB3.z;
        accB.w += wB0 * fB0.w + wB1 * fB1.w + wB2 * fB2.w + wB3 * fB3.w;
        wsumA += (wA0 + wA1) + (wA2 + wA3);
        wsumB += (wB0 + wB1) + (wB2 + wB3);
    }
    for (; k < deg; k++) {
        int s0 = __ldg(&colsrc[start + k]);
        float4 l0 = __ldg((const float4*)(el + (size_t)s0 * 4));
        float4 fA0 = *(const float4*)(ftA + (size_t)s0 * 256);
        float4 fB0 = *(const float4*)(ftB + (size_t)s0 * 256);
        float wA0 = leaky_exp((hlo ? l0.x : l0.y) + erA);
        float wB0 = leaky_exp((hlo ? l0.z : l0.w) + erB);
        accA.x += wA0 * fA0.x; accA.y += wA0 * fA0.y;
        accA.z += wA0 * fA0.z; accA.w += wA0 * fA0.w;
        accB.x += wB0 * fB0.x; accB.y += wB0 * fB0.y;
        accB.z += wB0 * fB0.z; accB.w += wB0 * fB0.w;
        wsumA += wA0; wsumB += wB0;
    }

    float invA = (deg > 0) ? (1.f / wsumA) : 0.f;
    float invB = (deg > 0) ? (1.f / wsumB) : 0.f;
    float4 bA = __ldg((const float4*)(bias + lane * 4));
    float4 bB = __ldg((const float4*)(bias + 128 + lane * 4));
    float4 oA, oB;
    oA.x = fmaxf(accA.x * invA + bA.x, 0.f);
    oA.y = fmaxf(accA.y * invA + bA.y, 0.f);
    oA.z = fmaxf(accA.z * invA + bA.z, 0.f);
    oA.w = fmaxf(accA.w * invA + bA.w, 0.f);
    oB.x = fmaxf(accB.x * invB + bB.x, 0.f);
    oB.y = fmaxf(accB.y * invB + bB.y, 0.f);
    oB.z = fmaxf(accB.z * invB + bB.z, 0.f);
    oB.w = fmaxf(accB.w * invB + bB.w, 0.f);
    *(float4*)(out + (size_t)n * 256 + lane * 4) = oA;
    *(float4*)(out + (size_t)n * 256 + 128 + lane * 4) = oB;
}

// layer 2: H=1, D=128, fp32 features. el/er as two partial arrays [2][Nn].
__global__ __launch_bounds__(256) void aggregate2_kernel(
    const float* __restrict__ ft, const float* __restrict__ elp, const float* __restrict__ erp,
    const int* __restrict__ rowptr, const int* __restrict__ colsrc,
    const float* __restrict__ bias, float* __restrict__ out, int Nn)
{
    int warp = threadIdx.x >> 5, lane = threadIdx.x & 31;
    int n = blockIdx.x * 8 + warp;
    if (n >= Nn) return;
    int start = rowptr[n];
    int deg = rowptr[n + 1] - start;

    float er_n = __ldg(&erp[n]) + __ldg(&erp[Nn + n]);
    float4 acc = make_float4(0.f, 0.f, 0.f, 0.f);
    float wsum = 0.f;
    const float* ftp = ft + lane * 4;

    int k = 0;
    for (; k + 8 <= deg; k += 8) {
        int s[8];
        #pragma unroll
        for (int u = 0; u < 8; u++) s[u] = __ldg(&colsrc[start + k + u]);
        float e[8];
        #pragma unroll
        for (int u = 0; u < 8; u++) e[u] = __ldg(&elp[s[u]]) + __ldg(&elp[Nn + s[u]]);
        float4 f[8];
        #pragma unroll
        for (int u = 0; u < 8; u++) f[u] = *(const float4*)(ftp + (size_t)s[u] * 128);
        #pragma unroll
        for (int u = 0; u < 8; u++) {
            float w = leaky_exp(e[u] + er_n);
            acc.x += w * f[u].x; acc.y += w * f[u].y;
            acc.z += w * f[u].z; acc.w += w * f[u].w;
            wsum += w;
        }
    }
    for (; k < deg; k++) {
        int s0 = __ldg(&colsrc[start + k]);
        float w = leaky_exp(__ldg(&elp[s0]) + __ldg(&elp[Nn + s0]) + er_n);
        float4 f0 = *(const float4*)(ftp + (size_t)s0 * 128);
        acc.x += w * f0.x; acc.y += w * f0.y;
        acc.z += w * f0.z; acc.w += w * f0.w;
        wsum += w;
    }

    float inv = (deg > 0) ? (1.f / wsum) : 0.f;
    float4 b = __ldg((const float4*)(bias + lane * 4));
    float4 o;
    o.x = acc.x * inv + b.x;
    o.y = acc.y * inv + b.y;
    o.z = acc.z * inv + b.z;
    o.w = acc.w * inv + b.w;
    *(float4*)(out + (size_t)n * 128 + lane * 4) = o;
}

// ---------------- launch (single stream) ----------------
extern "C" void kernel_launch(void* const* d_in, const int* in_sizes, int n_in,
                              void* d_out, int out_size)
{
    const float* feat    = (const float*)d_in[0];
    const int*   src     = (const int*)  d_in[1];
    const int*   dst     = (const int*)  d_in[2];
    const float* W1      = (const float*)d_in[3];
    const float* attn_l1 = (const float*)d_in[4];
    const float* attn_r1 = (const float*)d_in[5];
    const float* bias1   = (const float*)d_in[6];
    const float* W2      = (const float*)d_in[7];
    const float* attn_l2 = (const float*)d_in[8];
    const float* attn_r2 = (const float*)d_in[9];
    const float* bias2   = (const float*)d_in[10];
    float* out = (float*)d_out;

    float *ft1, *h1, *el1, *er1, *ft2, *el2p, *er2p;
    __half *wt1h, *wt1l, *wt2h, *wt2l;
    int *cnt, *rowptr, *colsrc;
    cudaGetSymbolAddress((void**)&ft1,    g_ft1);
    cudaGetSymbolAddress((void**)&h1,     g_h1);
    cudaGetSymbolAddress((void**)&el1,    g_el1);
    cudaGetSymbolAddress((void**)&er1,    g_er1);
    cudaGetSymbolAddress((void**)&ft2,    g_ft2);
    cudaGetSymbolAddress((void**)&el2p,   g_el2p);
    cudaGetSymbolAddress((void**)&er2p,   g_er2p);
    cudaGetSymbolAddress((void**)&wt1h,   g_wt1h);
    cudaGetSymbolAddress((void**)&wt1l,   g_wt1l);
    cudaGetSymbolAddress((void**)&wt2h,   g_wt2h);
    cudaGetSymbolAddress((void**)&wt2l,   g_wt2l);
    cudaGetSymbolAddress((void**)&cnt,    g_cnt);
    cudaGetSymbolAddress((void**)&rowptr, g_rowptr);
    cudaGetSymbolAddress((void**)&colsrc, g_colsrc);

    const int SMEM_SZ = (2 * 128 * 44) * 4 + (2 * 2 * 64 * 20) * 4;   // 65536
    cudaFuncSetAttribute(mma_gemm_f16_kernel<4>, cudaFuncAttributeMaxDynamicSharedMemorySize, SMEM_SZ);
    cudaFuncSetAttribute(mma_gemm_f16_kernel<1>, cudaFuncAttributeMaxDynamicSharedMemorySize, SMEM_SZ);

    transpose_split_kernel<<<384, 256>>>(W1, W2, wt1h, wt1l, wt2h, wt2l, cnt);     // 1 (+ zero cnt)
    count_dst_kernel<<<2048, 256>>>(dst, cnt, N_EDGES);                            // 2
    scan_kernel<<<1, 1024>>>(cnt, rowptr, N_NODES);                                // 3
    {                                                                              // 4: gemm1 (profiled)
        dim3 grid(4, (N_NODES + 127) / 128);
        mma_gemm_f16_kernel<4><<<grid, 256, SMEM_SZ>>>(feat, wt1h, wt1l, ft1,
                                                       attn_l1, attn_r1, el1, er1,
                                                       N_NODES, 256);
    }
    scatter_kernel<<<2048, 256>>>(src, dst, rowptr, cnt, colsrc, N_EDGES);         // 5
    aggregate1_kernel<<<(N_NODES + 7) / 8, 256>>>(ft1, el1, er1, rowptr, colsrc,   // 6
                                                  bias1, h1, N_NODES);
    {                                                                              // 7: gemm2
        dim3 grid(2, (N_NODES + 127) / 128);
        mma_gemm_f16_kernel<1><<<grid, 256, SMEM_SZ>>>(h1, wt2h, wt2l, ft2,
                                                       attn_l2, attn_r2, el2p, er2p,
                                                       N_NODES, 128);
    }
    aggregate2_kernel<<<(N_NODES + 7) / 8, 256>>>(ft2, el2p, er2p, rowptr, colsrc, // 8
                                                  bias2, out, N_NODES);
}

// round 13
// speedup vs baseline: 1.1358x; 1.1358x over previous
#include <cuda_runtime.h>
#include <cuda_fp16.h>
#include <math.h>
#include <stdint.h>

#define N_NODES 50000
#define N_EDGES 800000
#define NEG_SLOPE 0.2f
#define SCAN_NB ((N_NODES + 1023) / 1024)   // 49

// ---------------- scratch (device globals; no allocation allowed) ----------------
__device__ float  g_ft1[N_NODES * 256];
__device__ __half g_h1h[N_NODES * 256];    // layer-1 output, fp16 hi
__device__ __half g_h1l[N_NODES * 256];    // layer-1 output, fp16 lo (residual)
__device__ float  g_el1[N_NODES * 4];
__device__ float  g_er1[N_NODES * 4];
__device__ float  g_ft2[N_NODES * 128];
__device__ float  g_el2p[2 * N_NODES];
__device__ float  g_er2p[2 * N_NODES];
__device__ int    g_cnt[N_NODES];
__device__ int    g_rowptr[N_NODES + 1];
__device__ int    g_bsum[64];
__device__ int    g_colsrc[N_EDGES];
__device__ __half g_wt1h[256 * 256];   // W1^T hi fp16 [n][k]
__device__ __half g_wt1l[256 * 256];   // W1^T lo fp16
__device__ __half g_wt2h[128 * 256];   // W2^T hi
__device__ __half g_wt2l[128 * 256];   // W2^T lo

// ---------------- helpers ----------------
__device__ __forceinline__ uint32_t smem_u32(const void* p) {
    uint32_t a;
    asm("{ .reg .u64 t; cvta.to.shared.u64 t, %1; cvt.u32.u64 %0, t; }" : "=r"(a) : "l"(p));
    return a;
}

#define CP_ASYNC16(sa, gp) \
    asm volatile("cp.async.cg.shared.global [%0], [%1], 16;" :: "r"(sa), "l"(gp) : "memory")
#define CP_ASYNC16_Z(sa, gp, sz) \
    asm volatile("cp.async.cg.shared.global [%0], [%1], 16, %2;" :: "r"(sa), "l"(gp), "r"(sz) : "memory")
#define CP_COMMIT()  asm volatile("cp.async.commit_group;" ::: "memory")
#define CP_WAIT(n)   asm volatile("cp.async.wait_group %0;" :: "n"(n) : "memory")

#define MMA_F16(d, a0, a1, a2, a3, b0, b1)                                    \
    asm volatile("mma.sync.aligned.m16n8k16.row.col.f32.f16.f16.f32 "         \
                 "{%0,%1,%2,%3}, {%4,%5,%6,%7}, {%8,%9}, {%0,%1,%2,%3};"      \
                 : "+f"(d[0]), "+f"(d[1]), "+f"(d[2]), "+f"(d[3])             \
                 : "r"(a0), "r"(a1), "r"(a2), "r"(a3), "r"(b0), "r"(b1))

// split a float2 into packed fp16 hi + fp16 residual lo
__device__ __forceinline__ void split2(float2 x, uint32_t& h, uint32_t& l) {
    __half2 hh = __floats2half2_rn(x.x, x.y);
    float2 hf = __half22float2(hh);
    __half2 ll = __floats2half2_rn(x.x - hf.x, x.y - hf.y);
    h = *reinterpret_cast<uint32_t*>(&hh);
    l = *reinterpret_cast<uint32_t*>(&ll);
}

// ---------------- small utils ----------------
__global__ void count_dst_kernel(const int* __restrict__ dst, int* __restrict__ cnt, int E) {
    for (int e = blockIdx.x * blockDim.x + threadIdx.x; e < E; e += gridDim.x * blockDim.x)
        atomicAdd(&cnt[dst[e]], 1);
}

// transpose + fp16 hi/lo split of both weight matrices; also zeroes cnt[]
__global__ void transpose_split_kernel(const float* __restrict__ W1, const float* __restrict__ W2,
                                       __half* __restrict__ t1h, __half* __restrict__ t1l,
                                       __half* __restrict__ t2h, __half* __restrict__ t2l,
                                       int* __restrict__ cnt) {
    int t = blockIdx.x * blockDim.x + threadIdx.x;
    if (t < N_NODES) cnt[t] = 0;
    if (t < 65536) {
        int k = t & 255, n = t >> 8;
        float v = W1[k * 256 + n];
        __half h = __float2half_rn(v);
        t1h[n * 256 + k] = h;
        t1l[n * 256 + k] = __float2half_rn(v - __half2float(h));
    } else if (t < 98304) {
        int u = t - 65536;
        int k = u & 255, n = u >> 8;
        float v = W2[k * 128 + n];
        __half h = __float2half_rn(v);
        t2h[n * 256 + k] = h;
        t2l[n * 256 + k] = __float2half_rn(v - __half2float(h));
    }
}

// ---- parallel 3-phase scan ----
// phase 1: per-block inclusive scan of 1024-chunks -> rowptr[idx+1] (local), bsum[b]
__global__ __launch_bounds__(1024) void scan1_kernel(const int* __restrict__ cnt,
                                                     int* __restrict__ rowptr,
                                                     int* __restrict__ bsum, int n) {
    __shared__ int warp_sums[32];
    int tid = threadIdx.x, lane = tid & 31, warp = tid >> 5;
    int idx = blockIdx.x * 1024 + tid;
    int v = (idx < n) ? cnt[idx] : 0;
    int x = v;
    #pragma unroll
    for (int off = 1; off < 32; off <<= 1) {
        int y = __shfl_up_sync(0xffffffffu, x, off);
        if (lane >= off) x += y;
    }
    if (lane == 31) warp_sums[warp] = x;
    __syncthreads();
    if (warp == 0) {
        int s = warp_sums[lane];
        #pragma unroll
        for (int off = 1; off < 32; off <<= 1) {
            int y = __shfl_up_sync(0xffffffffu, s, off);
            if (lane >= off) s += y;
        }
        warp_sums[lane] = s;
    }
    __syncthreads();
    int incl = x + ((warp > 0) ? warp_sums[warp - 1] : 0);
    if (idx < n) rowptr[idx + 1] = incl;
    if (tid == 1023) bsum[blockIdx.x] = incl;
}

// phase 2: exclusive scan of block sums (tiny)
__global__ void scan2_kernel(int* __restrict__ bsum, int nb) {
    __shared__ int s[64];
    int tid = threadIdx.x;
    s[tid] = (tid < nb) ? bsum[tid] : 0;
    __syncthreads();
    if (tid == 0) {
        int acc = 0;
        for (int i = 0; i < nb; i++) { int t = s[i]; s[i] = acc; acc += t; }
    }
    __syncthreads();
    if (tid < nb) bsum[tid] = s[tid];
}

// phase 3: add block offsets; set rowptr[0]
__global__ void scan3_kernel(int* __restrict__ rowptr, const int* __restrict__ bsum, int n) {
    int idx = blockIdx.x * blockDim.x + threadIdx.x;
    if (idx == 0) rowptr[0] = 0;
    if (idx < n) rowptr[idx + 1] += bsum[idx >> 10];
}

__global__ void scatter_kernel(const int* __restrict__ src, const int* __restrict__ dst,
                               const int* __restrict__ rowptr, int* __restrict__ cnt,
                               int* __restrict__ colsrc, int E) {
    for (int e = blockIdx.x * blockDim.x + threadIdx.x; e < E; e += gridDim.x * blockDim.x) {
        int d = dst[e];
        int pos = atomicSub(&cnt[d], 1);
        colsrc[rowptr[d] + pos - 1] = src[e];
    }
}

// ---------------- fp16 split-MMA GEMM, fp32 A (layer 1) + fused el/er ----------------
// ASTR=40: LDS.64 fragment loads conflict-free per 16-lane phase ((4g+q) mod 16 distinct).
__global__ __launch_bounds__(256, 3) void mma_gemm_f16_kernel(
    const float* __restrict__ A,
    const __half* __restrict__ Bth, const __half* __restrict__ Btl,
    float* __restrict__ C,
    const float* __restrict__ attn_l, const float* __restrict__ attn_r,
    float* __restrict__ el, float* __restrict__ er,
    int M, int Nc)
{
    const int BM = 128, BN = 64, BK = 32, K = 256;
    const int ASTR = 40;
    const int BSTR2 = 20;
    extern __shared__ float sm[];
    float*   As  = sm;                                    // [2][BM][40] f32
    __half2* Bh2 = (__half2*)(As + 2 * BM * ASTR);        // [2][BN][20] half2 hi
    __half2* Bl2 = Bh2 + 2 * BN * BSTR2;                  // [2][BN][20] half2 lo

    uint32_t as_b = smem_u32(As);
    uint32_t bh_b = smem_u32(Bh2);
    uint32_t bl_b = smem_u32(Bl2);

    int tid = threadIdx.x, lane = tid & 31, warp = tid >> 5;
    int blockRow = blockIdx.y * BM;
    int blockCol = blockIdx.x * BN;
    int g = lane >> 2, q = lane & 3;

    float acc[8][4];
    #pragma unroll
    for (int j = 0; j < 8; j++)
        #pragma unroll
        for (int c = 0; c < 4; c++) acc[j][c] = 0.f;

    auto load_tile = [&](int t) {
        int buf = t & 1, k0 = t * BK;
        #pragma unroll
        for (int l = 0; l < 4; l++) {
            int c = tid + l * 256;
            int r = c >> 3, kq = (c & 7) * 4;
            const float* gp = A + (size_t)(blockRow + r) * K + k0 + kq;
            uint32_t sa = as_b + (uint32_t)(((buf * BM + r) * ASTR + kq) * 4);
            uint32_t sz = (blockRow + r < M) ? 16u : 0u;
            CP_ASYNC16_Z(sa, gp, sz);
        }
        {
            int n = tid >> 2, ch = tid & 3;
            size_t go = (size_t)(blockCol + n) * K + k0 + ch * 8;
            uint32_t so = (uint32_t)(((buf * BN + n) * BSTR2 + ch * 4) * 4);
            CP_ASYNC16(bh_b + so, Bth + go);
            CP_ASYNC16(bl_b + so, Btl + go);
        }
        CP_COMMIT();
    };

    load_tile(0);

    #pragma unroll 1
    for (int t = 0; t < K / BK; t++) {
        if (t < K / BK - 1) {
            load_tile(t + 1);
            CP_WAIT(1);
        } else {
            CP_WAIT(0);
        }
        __syncthreads();

        int buf = t & 1;
        const float2*  Af2 = (const float2*)(As + buf * BM * ASTR);
        const __half2* Bhb = Bh2 + buf * BN * BSTR2;
        const __half2* Blb = Bl2 + buf * BN * BSTR2;

        #pragma unroll
        for (int ks = 0; ks < 2; ks++) {
            int kof = ks * 8;
            int r0 = warp * 16 + g;
            uint32_t ah[4], al[4];
            float2 x00 = Af2[(r0    ) * 20 + kof + q];
            float2 x10 = Af2[(r0 + 8) * 20 + kof + q];
            float2 x01 = Af2[(r0    ) * 20 + kof + q + 4];
            float2 x11 = Af2[(r0 + 8) * 20 + kof + q + 4];
            split2(x00, ah[0], al[0]);
            split2(x10, ah[1], al[1]);
            split2(x01, ah[2], al[2]);
            split2(x11, ah[3], al[3]);
            #pragma unroll
            for (int j = 0; j < 8; j++) {
                int nb = j * 8 + g;
                uint32_t b0h = *reinterpret_cast<const uint32_t*>(&Bhb[nb * BSTR2 + kof + q]);
                uint32_t b1h = *reinterpret_cast<const uint32_t*>(&Bhb[nb * BSTR2 + kof + q + 4]);
                uint32_t b0l = *reinterpret_cast<const uint32_t*>(&Blb[nb * BSTR2 + kof + q]);
                uint32_t b1l = *reinterpret_cast<const uint32_t*>(&Blb[nb * BSTR2 + kof + q + 4]);
                MMA_F16(acc[j], ah[0], ah[1], ah[2], ah[3], b0h, b1h);
                MMA_F16(acc[j], al[0], al[1], al[2], al[3], b0h, b1h);
                MMA_F16(acc[j], ah[0], ah[1], ah[2], ah[3], b0l, b1l);
            }
        }
        __syncthreads();
    }

    // ---- store C (fp32) ----
    int r0 = blockRow + warp * 16 + g;
    int r1 = r0 + 8;
    #pragma unroll
    for (int j = 0; j < 8; j++) {
        int c = blockCol + j * 8 + q * 2;
        if (r0 < M) *(float2*)(C + (size_t)r0 * Nc + c) = make_float2(acc[j][0], acc[j][1]);
        if (r1 < M) *(float2*)(C + (size_t)r1 * Nc + c) = make_float2(acc[j][2], acc[j][3]);
    }

    // ---- fused el/er epilogue (HEADS=4: head = blockIdx.x) ----
    float pl0 = 0.f, pl1 = 0.f, pr0 = 0.f, pr1 = 0.f;
    #pragma unroll
    for (int j = 0; j < 8; j++) {
        int idx = blockCol + j * 8 + q * 2;
        float a0 = __ldg(&attn_l[idx]), a1 = __ldg(&attn_l[idx + 1]);
        float b0 = __ldg(&attn_r[idx]), b1 = __ldg(&attn_r[idx + 1]);
        pl0 += acc[j][0] * a0 + acc[j][1] * a1;
        pl1 += acc[j][2] * a0 + acc[j][3] * a1;
        pr0 += acc[j][0] * b0 + acc[j][1] * b1;
        pr1 += acc[j][2] * b0 + acc[j][3] * b1;
    }
    #pragma unroll
    for (int off = 1; off <= 2; off <<= 1) {
        pl0 += __shfl_xor_sync(0xffffffffu, pl0, off);
        pl1 += __shfl_xor_sync(0xffffffffu, pl1, off);
        pr0 += __shfl_xor_sync(0xffffffffu, pr0, off);
        pr1 += __shfl_xor_sync(0xffffffffu, pr1, off);
    }
    if (q == 0) {
        if (r0 < M) {
            el[(size_t)r0 * 4 + blockIdx.x] = pl0;
            er[(size_t)r0 * 4 + blockIdx.x] = pr0;
        }
        if (r1 < M) {
            el[(size_t)r1 * 4 + blockIdx.x] = pl1;
            er[(size_t)r1 * 4 + blockIdx.x] = pr1;
        }
    }
}

// ---------------- fp16-A split-MMA GEMM (layer 2: A pre-split by agg1) ----------------
__global__ __launch_bounds__(256, 3) void mma_gemm_f16a_kernel(
    const __half* __restrict__ Ath, const __half* __restrict__ Atl,
    const __half* __restrict__ Bth, const __half* __restrict__ Btl,
    float* __restrict__ C,
    const float* __restrict__ attn_l, const float* __restrict__ attn_r,
    float* __restrict__ el, float* __restrict__ er,
    int M, int Nc)
{
    const int BM = 128, BN = 64, BK = 32, K = 256;
    const int STR2 = 20;   // half2 per row (16 data + 4 pad) -> conflict-free 32-bit LDS
    extern __shared__ float sm[];
    __half2* Ah2 = (__half2*)sm;                  // [2][BM][20] hi
    __half2* Al2 = Ah2 + 2 * BM * STR2;           // [2][BM][20] lo
    __half2* Bh2 = Al2 + 2 * BM * STR2;           // [2][BN][20] hi
    __half2* Bl2 = Bh2 + 2 * BN * STR2;           // [2][BN][20] lo

    uint32_t ah_b = smem_u32(Ah2);
    uint32_t al_b = smem_u32(Al2);
    uint32_t bh_b = smem_u32(Bh2);
    uint32_t bl_b = smem_u32(Bl2);

    int tid = threadIdx.x, lane = tid & 31, warp = tid >> 5;
    int blockRow = blockIdx.y * BM;
    int blockCol = blockIdx.x * BN;
    int g = lane >> 2, q = lane & 3;

    float acc[8][4];
    #pragma unroll
    for (int j = 0; j < 8; j++)
        #pragma unroll
        for (int c = 0; c < 4; c++) acc[j][c] = 0.f;

    auto load_tile = [&](int t) {
        int buf = t & 1, k0 = t * BK;
        // A: 128 rows x 32 halves = 4 chunks/row -> 512 chunks, 2 per thread (hi + lo)
        #pragma unroll
        for (int l = 0; l < 2; l++) {
            int c = tid + l * 256;
            int r = c >> 2, ch = c & 3;
            size_t go = (size_t)(blockRow + r) * K + k0 + ch * 8;
            uint32_t so = (uint32_t)(((buf * BM + r) * STR2 + ch * 4) * 4);
            uint32_t sz = (blockRow + r < M) ? 16u : 0u;
            CP_ASYNC16_Z(ah_b + so, Ath + go, sz);
            CP_ASYNC16_Z(al_b + so, Atl + go, sz);
        }
        // B: 64 rows x 32 halves -> 256 chunks, 1 per thread (hi + lo)
        {
            int n = tid >> 2, ch = tid & 3;
            size_t go = (size_t)(blockCol + n) * K + k0 + ch * 8;
            uint32_t so = (uint32_t)(((buf * BN + n) * STR2 + ch * 4) * 4);
            CP_ASYNC16(bh_b + so, Bth + go);
            CP_ASYNC16(bl_b + so, Btl + go);
        }
        CP_COMMIT();
    };

    load_tile(0);

    #pragma unroll 1
    for (int t = 0; t < K / BK; t++) {
        if (t < K / BK - 1) {
            load_tile(t + 1);
            CP_WAIT(1);
        } else {
            CP_WAIT(0);
        }
        __syncthreads();

        int buf = t & 1;
        const __half2* Ahb = Ah2 + buf * BM * STR2;
        const __half2* Alb = Al2 + buf * BM * STR2;
        const __half2* Bhb = Bh2 + buf * BN * STR2;
        const __half2* Blb = Bl2 + buf * BN * STR2;

        #pragma unroll
        for (int ks = 0; ks < 2; ks++) {
            int kof = ks * 8;
            int r0 = warp * 16 + g;
            uint32_t ah[4], al[4];
            ah[0] = *reinterpret_cast<const uint32_t*>(&Ahb[(r0    ) * STR2 + kof + q]);
            ah[1] = *reinterpret_cast<const uint32_t*>(&Ahb[(r0 + 8) * STR2 + kof + q]);
            ah[2] = *reinterpret_cast<const uint32_t*>(&Ahb[(r0    ) * STR2 + kof + q + 4]);
            ah[3] = *reinterpret_cast<const uint32_t*>(&Ahb[(r0 + 8) * STR2 + kof + q + 4]);
            al[0] = *reinterpret_cast<const uint32_t*>(&Alb[(r0    ) * STR2 + kof + q]);
            al[1] = *reinterpret_cast<const uint32_t*>(&Alb[(r0 + 8) * STR2 + kof + q]);
            al[2] = *reinterpret_cast<const uint32_t*>(&Alb[(r0    ) * STR2 + kof + q + 4]);
            al[3] = *reinterpret_cast<const uint32_t*>(&Alb[(r0 + 8) * STR2 + kof + q + 4]);
            #pragma unroll
            for (int j = 0; j < 8; j++) {
                int nb = j * 8 + g;
                uint32_t b0h = *reinterpret_cast<const uint32_t*>(&Bhb[nb * STR2 + kof + q]);
                uint32_t b1h = *reinterpret_cast<const uint32_t*>(&Bhb[nb * STR2 + kof + q + 4]);
                uint32_t b0l = *reinterpret_cast<const uint32_t*>(&Blb[nb * STR2 + kof + q]);
                uint32_t b1l = *reinterpret_cast<const uint32_t*>(&Blb[nb * STR2 + kof + q + 4]);
                MMA_F16(acc[j], ah[0], ah[1], ah[2], ah[3], b0h, b1h);
                MMA_F16(acc[j], al[0], al[1], al[2], al[3], b0h, b1h);
                MMA_F16(acc[j], ah[0], ah[1], ah[2], ah[3], b0l, b1l);
            }
        }
        __syncthreads();
    }

    // ---- store C (fp32) ----
    int r0 = blockRow + warp * 16 + g;
    int r1 = r0 + 8;
    #pragma unroll
    for (int j = 0; j < 8; j++) {
        int c = blockCol + j * 8 + q * 2;
        if (r0 < M) *(float2*)(C + (size_t)r0 * Nc + c) = make_float2(acc[j][0], acc[j][1]);
        if (r1 < M) *(float2*)(C + (size_t)r1 * Nc + c) = make_float2(acc[j][2], acc[j][3]);
    }

    // ---- fused el/er epilogue (HEADS=1: partial arrays [blockIdx.x][M]) ----
    float pl0 = 0.f, pl1 = 0.f, pr0 = 0.f, pr1 = 0.f;
    #pragma unroll
    for (int j = 0; j < 8; j++) {
        int idx = blockCol + j * 8 + q * 2;
        float a0 = __ldg(&attn_l[idx]), a1 = __ldg(&attn_l[idx + 1]);
        float b0 = __ldg(&attn_r[idx]), b1 = __ldg(&attn_r[idx + 1]);
        pl0 += acc[j][0] * a0 + acc[j][1] * a1;
        pl1 += acc[j][2] * a0 + acc[j][3] * a1;
        pr0 += acc[j][0] * b0 + acc[j][1] * b1;
        pr1 += acc[j][2] * b0 + acc[j][3] * b1;
    }
    #pragma unroll
    for (int off = 1; off <= 2; off <<= 1) {
        pl0 += __shfl_xor_sync(0xffffffffu, pl0, off);
        pl1 += __shfl_xor_sync(0xffffffffu, pl1, off);
        pr0 += __shfl_xor_sync(0xffffffffu, pr0, off);
        pr1 += __shfl_xor_sync(0xffffffffu, pr1, off);
    }
    if (q == 0) {
        if (r0 < M) {
            el[(size_t)blockIdx.x * M + r0] = pl0;
            er[(size_t)blockIdx.x * M + r0] = pr0;
        }
        if (r1 < M) {
            el[(size_t)blockIdx.x * M + r1] = pl1;
            er[(size_t)blockIdx.x * M + r1] = pr1;
        }
    }
}

// ---------------- fused softmax + aggregation ----------------
__device__ __forceinline__ float leaky_exp(float e) {
    e = (e > 0.f) ? e : NEG_SLOPE * e;
    return __expf(e);
}

// layer 1: H=4, D=64, C=256, fp32 features. One warp per node.
// Output h1 written directly as fp16 hi/lo split (consumed by gemm2's fp16-A path).
__global__ __launch_bounds__(256) void aggregate1_kernel(
    const float* __restrict__ ft, const float* __restrict__ el, const float* __restrict__ er,
    const int* __restrict__ rowptr, const int* __restrict__ colsrc,
    const float* __restrict__ bias, __half* __restrict__ outh, __half* __restrict__ outl, int Nn)
{
    int warp = threadIdx.x >> 5, lane = threadIdx.x & 31;
    int n = blockIdx.x * 8 + warp;
    if (n >= Nn) return;
    int start = rowptr[n];
    int deg = rowptr[n + 1] - start;

    const bool hlo = (lane < 16);
    float4 er4 = __ldg((const float4*)(er + (size_t)n * 4));
    float erA = hlo ? er4.x : er4.y;
    float erB = hlo ? er4.z : er4.w;

    float4 accA = make_float4(0.f, 0.f, 0.f, 0.f);
    float4 accB = make_float4(0.f, 0.f, 0.f, 0.f);
    float wsumA = 0.f, wsumB = 0.f;
    const float* ftA = ft + lane * 4;
    const float* ftB = ft + 128 + lane * 4;

    int k = 0;
    for (; k + 4 <= deg; k += 4) {
        int s0 = __ldg(&colsrc[start + k + 0]);
        int s1 = __ldg(&colsrc[start + k + 1]);
        int s2 = __ldg(&colsrc[start + k + 2]);
        int s3 = __ldg(&colsrc[start + k + 3]);
        float4 l0 = __ldg((const float4*)(el + (size_t)s0 * 4));
        float4 l1 = __ldg((const float4*)(el + (size_t)s1 * 4));
        float4 l2 = __ldg((const float4*)(el + (size_t)s2 * 4));
        float4 l3 = __ldg((const float4*)(el + (size_t)s3 * 4));
        float4 fA0 = *(const float4*)(ftA + (size_t)s0 * 256);
        float4 fB0 = *(const float4*)(ftB + (size_t)s0 * 256);
        float4 fA1 = *(const float4*)(ftA + (size_t)s1 * 256);
        float4 fB1 = *(const float4*)(ftB + (size_t)s1 * 256);
        float4 fA2 = *(const float4*)(ftA + (size_t)s2 * 256);
        float4 fB2 = *(const float4*)(ftB + (size_t)s2 * 256);
        float4 fA3 = *(const float4*)(ftA + (size_t)s3 * 256);
        float4 fB3 = *(const float4*)(ftB + (size_t)s3 * 256);
        float wA0 = leaky_exp((hlo ? l0.x : l0.y) + erA);
        float wB0 = leaky_exp((hlo ? l0.z : l0.w) + erB);
        float wA1 = leaky_exp((hlo ? l1.x : l1.y) + erA);
        float wB1 = leaky_exp((hlo ? l1.z : l1.w) + erB);
        float wA2 = leaky_exp((hlo ? l2.x : l2.y) + erA);
        float wB2 = leaky_exp((hlo ? l2.z : l2.w) + erB);
        float wA3 = leaky_exp((hlo ? l3.x : l3.y) + erA);
        float wB3 = leaky_exp((hlo ? l3.z : l3.w) + erB);
        accA.x += wA0 * fA0.x + wA1 * fA1.x + wA2 * fA2.x + wA3 * fA3.x;
        accA.y += wA0 * fA0.y + wA1 * fA1.y + wA2 * fA2.y + wA3 * fA3.y;
        accA.z += wA0 * fA0.z + wA1 * fA1.z + wA2 * fA2.z + wA3 * fA3.z;
        accA.w += wA0 * fA0.w + wA1 * fA1.w + wA2 * fA2.w + wA3 * fA3.w;
        accB.x += wB0 * fB0.x + wB1 * fB1.x + wB2 * fB2.x + wB3 * fB3.x;
        accB.y += wB0 * fB0.y + wB1 * fB1.y + wB2 * fB2.y + wB3 * fB3.y;
        accB.z += wB0 * fB0.z + wB1 * fB1.z + wB2 * fB2.z + wB3 * fB3.z;
        accB.w += wB0 * fB0.w + wB1 * fB1.w + wB2 * fB2.w + wB3 * fB3.w;
        wsumA += (wA0 + wA1) + (wA2 + wA3);
        wsumB += (wB0 + wB1) + (wB2 + wB3);
    }
    for (; k < deg; k++) {
        int s0 = __ldg(&colsrc[start + k]);
        float4 l0 = __ldg((const float4*)(el + (size_t)s0 * 4));
        float4 fA0 = *(const float4*)(ftA + (size_t)s0 * 256);
        float4 fB0 = *(const float4*)(ftB + (size_t)s0 * 256);
        float wA0 = leaky_exp((hlo ? l0.x : l0.y) + erA);
        float wB0 = leaky_exp((hlo ? l0.z : l0.w) + erB);
        accA.x += wA0 * fA0.x; accA.y += wA0 * fA0.y;
        accA.z += wA0 * fA0.z; accA.w += wA0 * fA0.w;
        accB.x += wB0 * fB0.x; accB.y += wB0 * fB0.y;
        accB.z += wB0 * fB0.z; accB.w += wB0 * fB0.w;
        wsumA += wA0; wsumB += wB0;
    }

    float invA = (deg > 0) ? (1.f / wsumA) : 0.f;
    float invB = (deg > 0) ? (1.f / wsumB) : 0.f;
    float4 bA = __ldg((const float4*)(bias + lane * 4));
    float4 bB = __ldg((const float4*)(bias + 128 + lane * 4));
    float4 oA, oB;
    oA.x = fmaxf(accA.x * invA + bA.x, 0.f);
    oA.y = fmaxf(accA.y * invA + bA.y, 0.f);
    oA.z = fmaxf(accA.z * invA + bA.z, 0.f);
    oA.w = fmaxf(accA.w * invA + bA.w, 0.f);
    oB.x = fmaxf(accB.x * invB + bB.x, 0.f);
    oB.y = fmaxf(accB.y * invB + bB.y, 0.f);
    oB.z = fmaxf(accB.z * invB + bB.z, 0.f);
    oB.w = fmaxf(accB.w * invB + bB.w, 0.f);

    // fp16 hi/lo split store (identical arithmetic to gemm2-side split)
    uint32_t hA0, lA0, hA1, lA1, hB0, lB0, hB1, lB1;
    split2(make_float2(oA.x, oA.y), hA0, lA0);
    split2(make_float2(oA.z, oA.w), hA1, lA1);
    split2(make_float2(oB.x, oB.y), hB0, lB0);
    split2(make_float2(oB.z, oB.w), hB1, lB1);
    *(uint2*)(outh + (size_t)n * 256 + lane * 4)       = make_uint2(hA0, hA1);
    *(uint2*)(outl + (size_t)n * 256 + lane * 4)       = make_uint2(lA0, lA1);
    *(uint2*)(outh + (size_t)n * 256 + 128 + lane * 4) = make_uint2(hB0, hB1);
    *(uint2*)(outl + (size_t)n * 256 + 128 + lane * 4) = make_uint2(lB0, lB1);
}

// layer 2: H=1, D=128, fp32 features. el/er as two partial arrays [2][Nn].
__global__ __launch_bounds__(256) void aggregate2_kernel(
    const float* __restrict__ ft, const float* __restrict__ elp, const float* __restrict__ erp,
    const int* __restrict__ rowptr, const int* __restrict__ colsrc,
    const float* __restrict__ bias, float* __restrict__ out, int Nn)
{
    int warp = threadIdx.x >> 5, lane = threadIdx.x & 31;
    int n = blockIdx.x * 8 + warp;
    if (n >= Nn) return;
    int start = rowptr[n];
    int deg = rowptr[n + 1] - start;

    float er_n = __ldg(&erp[n]) + __ldg(&erp[Nn + n]);
    float4 acc = make_float4(0.f, 0.f, 0.f, 0.f);
    float wsum = 0.f;
    const float* ftp = ft + lane * 4;

    int k = 0;
    for (; k + 8 <= deg; k += 8) {
        int s[8];
        #pragma unroll
        for (int u = 0; u < 8; u++) s[u] = __ldg(&colsrc[start + k + u]);
        float e[8];
        #pragma unroll
        for (int u = 0; u < 8; u++) e[u] = __ldg(&elp[s[u]]) + __ldg(&elp[Nn + s[u]]);
        float4 f[8];
        #pragma unroll
        for (int u = 0; u < 8; u++) f[u] = *(const float4*)(ftp + (size_t)s[u] * 128);
        #pragma unroll
        for (int u = 0; u < 8; u++) {
            float w = leaky_exp(e[u] + er_n);
            acc.x += w * f[u].x; acc.y += w * f[u].y;
            acc.z += w * f[u].z; acc.w += w * f[u].w;
            wsum += w;
        }
    }
    for (; k < deg; k++) {
        int s0 = __ldg(&colsrc[start + k]);
        float w = leaky_exp(__ldg(&elp[s0]) + __ldg(&elp[Nn + s0]) + er_n);
        float4 f0 = *(const float4*)(ftp + (size_t)s0 * 128);
        acc.x += w * f0.x; acc.y += w * f0.y;
        acc.z += w * f0.z; acc.w += w * f0.w;
        wsum += w;
    }

    float inv = (deg > 0) ? (1.f / wsum) : 0.f;
    float4 b = __ldg((const float4*)(bias + lane * 4));
    float4 o;
    o.x = acc.x * inv + b.x;
    o.y = acc.y * inv + b.y;
    o.z = acc.z * inv + b.z;
    o.w = acc.w * inv + b.w;
    *(float4*)(out + (size_t)n * 128 + lane * 4) = o;
}

// ---------------- launch (single stream) ----------------
extern "C" void kernel_launch(void* const* d_in, const int* in_sizes, int n_in,
                              void* d_out, int out_size)
{
    const float* feat    = (const float*)d_in[0];
    const int*   src     = (const int*)  d_in[1];
    const int*   dst     = (const int*)  d_in[2];
    const float* W1      = (const float*)d_in[3];
    const float* attn_l1 = (const float*)d_in[4];
    const float* attn_r1 = (const float*)d_in[5];
    const float* bias1   = (const float*)d_in[6];
    const float* W2      = (const float*)d_in[7];
    const float* attn_l2 = (const float*)d_in[8];
    const float* attn_r2 = (const float*)d_in[9];
    const float* bias2   = (const float*)d_in[10];
    float* out = (float*)d_out;

    float *ft1, *el1, *er1, *ft2, *el2p, *er2p;
    __half *h1h, *h1l, *wt1h, *wt1l, *wt2h, *wt2l;
    int *cnt, *rowptr, *colsrc, *bsum;
    cudaGetSymbolAddress((void**)&ft1,    g_ft1);
    cudaGetSymbolAddress((void**)&h1h,    g_h1h);
    cudaGetSymbolAddress((void**)&h1l,    g_h1l);
    cudaGetSymbolAddress((void**)&el1,    g_el1);
    cudaGetSymbolAddress((void**)&er1,    g_er1);
    cudaGetSymbolAddress((void**)&ft2,    g_ft2);
    cudaGetSymbolAddress((void**)&el2p,   g_el2p);
    cudaGetSymbolAddress((void**)&er2p,   g_er2p);
    cudaGetSymbolAddress((void**)&wt1h,   g_wt1h);
    cudaGetSymbolAddress((void**)&wt1l,   g_wt1l);
    cudaGetSymbolAddress((void**)&wt2h,   g_wt2h);
    cudaGetSymbolAddress((void**)&wt2l,   g_wt2l);
    cudaGetSymbolAddress((void**)&cnt,    g_cnt);
    cudaGetSymbolAddress((void**)&rowptr, g_rowptr);
    cudaGetSymbolAddress((void**)&colsrc, g_colsrc);
    cudaGetSymbolAddress((void**)&bsum,   g_bsum);

    const int SMEM_SZ  = (2 * 128 * 40) * 4 + (2 * 2 * 64 * 20) * 4;                 // 61440
    const int SMEM_SZA = (2 * 2 * 128 * 20) * 4 + (2 * 2 * 64 * 20) * 4;             // 61440
    cudaFuncSetAttribute(mma_gemm_f16_kernel,  cudaFuncAttributeMaxDynamicSharedMemorySize, SMEM_SZ);
    cudaFuncSetAttribute(mma_gemm_f16a_kernel, cudaFuncAttributeMaxDynamicSharedMemorySize, SMEM_SZA);

    transpose_split_kernel<<<384, 256>>>(W1, W2, wt1h, wt1l, wt2h, wt2l, cnt);     // 1 (+ zero cnt)
    count_dst_kernel<<<2048, 256>>>(dst, cnt, N_EDGES);                            // 2
    scan1_kernel<<<SCAN_NB, 1024>>>(cnt, rowptr, bsum, N_NODES);                   // 3
    {                                                                              // 4: gemm1 (profiled)
        dim3 grid(4, (N_NODES + 127) / 128);
        mma_gemm_f16_kernel<<<grid, 256, SMEM_SZ>>>(feat, wt1h, wt1l, ft1,
                                                    attn_l1, attn_r1, el1, er1,
                                                    N_NODES, 256);
    }
    scan2_kernel<<<1, 64>>>(bsum, SCAN_NB);                                        // 5
    scan3_kernel<<<(N_NODES + 255) / 256, 256>>>(rowptr, bsum, N_NODES);           // 6
    scatter_kernel<<<2048, 256>>>(src, dst, rowptr, cnt, colsrc, N_EDGES);         // 7
    aggregate1_kernel<<<(N_NODES + 7) / 8, 256>>>(ft1, el1, er1, rowptr, colsrc,   // 8
                                                  bias1, h1h, h1l, N_NODES);
    {                                                                              // 9: gemm2 (fp16 A)
        dim3 grid(2, (N_NODES + 127) / 128);
        mma_gemm_f16a_kernel<<<grid, 256, SMEM_SZA>>>(h1h, h1l, wt2h, wt2l, ft2,
                                                      attn_l2, attn_r2, el2p, er2p,
                                                      N_NODES, 128);
    }
    aggregate2_kernel<<<(N_NODES + 7) / 8, 256>>>(ft2, el2p, er2p, rowptr, colsrc, // 10
                                                  bias2, out, N_NODES);
}

// round 14
// speedup vs baseline: 1.1947x; 1.0518x over previous
#include <cuda_runtime.h>
#include <cuda_fp16.h>
#include <math.h>
#include <stdint.h>

#define N_NODES 50000
#define N_EDGES 800000
#define NEG_SLOPE 0.2f
#define SCAN_NB ((N_NODES + 1023) / 1024)   // 49

// ---------------- scratch (device globals; no allocation allowed) ----------------
__device__ float  g_ft1[N_NODES * 256];
__device__ __half g_h1h[N_NODES * 256];    // layer-1 output, fp16 hi
__device__ __half g_h1l[N_NODES * 256];    // layer-1 output, fp16 lo (residual)
__device__ float  g_el1[N_NODES * 4];
__device__ float  g_er1[N_NODES * 4];
__device__ float  g_ft2[N_NODES * 128];
__device__ float  g_el2[N_NODES];
__device__ float  g_er2[N_NODES];
__device__ int    g_cnt[N_NODES];
__device__ int    g_rowptr[N_NODES + 1];
__device__ int    g_bsum[64];
__device__ int    g_colsrc[N_EDGES];
__device__ __half g_wt1h[256 * 256];   // W1^T hi fp16 [n][k]
__device__ __half g_wt1l[256 * 256];   // W1^T lo fp16
__device__ __half g_wt2h[128 * 256];   // W2^T hi
__device__ __half g_wt2l[128 * 256];   // W2^T lo

// ---------------- helpers ----------------
__device__ __forceinline__ uint32_t smem_u32(const void* p) {
    uint32_t a;
    asm("{ .reg .u64 t; cvta.to.shared.u64 t, %1; cvt.u32.u64 %0, t; }" : "=r"(a) : "l"(p));
    return a;
}

#define CP_ASYNC16(sa, gp) \
    asm volatile("cp.async.cg.shared.global [%0], [%1], 16;" :: "r"(sa), "l"(gp) : "memory")
#define CP_ASYNC16_Z(sa, gp, sz) \
    asm volatile("cp.async.cg.shared.global [%0], [%1], 16, %2;" :: "r"(sa), "l"(gp), "r"(sz) : "memory")
#define CP_COMMIT()  asm volatile("cp.async.commit_group;" ::: "memory")
#define CP_WAIT(n)   asm volatile("cp.async.wait_group %0;" :: "n"(n) : "memory")

#define MMA_F16(d, a0, a1, a2, a3, b0, b1)                                    \
    asm volatile("mma.sync.aligned.m16n8k16.row.col.f32.f16.f16.f32 "         \
                 "{%0,%1,%2,%3}, {%4,%5,%6,%7}, {%8,%9}, {%0,%1,%2,%3};"      \
                 : "+f"(d[0]), "+f"(d[1]), "+f"(d[2]), "+f"(d[3])             \
                 : "r"(a0), "r"(a1), "r"(a2), "r"(a3), "r"(b0), "r"(b1))

#define LDSM_X4(r0, r1, r2, r3, addr)                                         \
    asm volatile("ldmatrix.sync.aligned.m8n8.x4.shared.b16 {%0,%1,%2,%3}, [%4];" \
                 : "=r"(r0), "=r"(r1), "=r"(r2), "=r"(r3) : "r"(addr))

// split a float2 into packed fp16 hi + fp16 residual lo
__device__ __forceinline__ void split2(float2 x, uint32_t& h, uint32_t& l) {
    __half2 hh = __floats2half2_rn(x.x, x.y);
    float2 hf = __half22float2(hh);
    __half2 ll = __floats2half2_rn(x.x - hf.x, x.y - hf.y);
    h = *reinterpret_cast<uint32_t*>(&hh);
    l = *reinterpret_cast<uint32_t*>(&ll);
}

// ---------------- small utils ----------------
__global__ void count_dst_kernel(const int* __restrict__ dst, int* __restrict__ cnt, int E) {
    for (int e = blockIdx.x * blockDim.x + threadIdx.x; e < E; e += gridDim.x * blockDim.x)
        atomicAdd(&cnt[dst[e]], 1);
}

// transpose + fp16 hi/lo split of both weight matrices; zeroes cnt[] and el2/er2
__global__ void transpose_split_kernel(const float* __restrict__ W1, const float* __restrict__ W2,
                                       __half* __restrict__ t1h, __half* __restrict__ t1l,
                                       __half* __restrict__ t2h, __half* __restrict__ t2l,
                                       int* __restrict__ cnt,
                                       float* __restrict__ el2, float* __restrict__ er2) {
    int t = blockIdx.x * blockDim.x + threadIdx.x;
    if (t < N_NODES) { cnt[t] = 0; el2[t] = 0.f; er2[t] = 0.f; }
    if (t < 65536) {
        int k = t & 255, n = t >> 8;
        float v = W1[k * 256 + n];
        __half h = __float2half_rn(v);
        t1h[n * 256 + k] = h;
        t1l[n * 256 + k] = __float2half_rn(v - __half2float(h));
    } else if (t < 98304) {
        int u = t - 65536;
        int k = u & 255, n = u >> 8;
        float v = W2[k * 128 + n];
        __half h = __float2half_rn(v);
        t2h[n * 256 + k] = h;
        t2l[n * 256 + k] = __float2half_rn(v - __half2float(h));
    }
}

// ---- parallel 3-phase scan ----
__global__ __launch_bounds__(1024) void scan1_kernel(const int* __restrict__ cnt,
                                                     int* __restrict__ rowptr,
                                                     int* __restrict__ bsum, int n) {
    __shared__ int warp_sums[32];
    int tid = threadIdx.x, lane = tid & 31, warp = tid >> 5;
    int idx = blockIdx.x * 1024 + tid;
    int v = (idx < n) ? cnt[idx] : 0;
    int x = v;
    #pragma unroll
    for (int off = 1; off < 32; off <<= 1) {
        int y = __shfl_up_sync(0xffffffffu, x, off);
        if (lane >= off) x += y;
    }
    if (lane == 31) warp_sums[warp] = x;
    __syncthreads();
    if (warp == 0) {
        int s = warp_sums[lane];
        #pragma unroll
        for (int off = 1; off < 32; off <<= 1) {
            int y = __shfl_up_sync(0xffffffffu, s, off);
            if (lane >= off) s += y;
        }
        warp_sums[lane] = s;
    }
    __syncthreads();
    int incl = x + ((warp > 0) ? warp_sums[warp - 1] : 0);
    if (idx < n) rowptr[idx + 1] = incl;
    if (tid == 1023) bsum[blockIdx.x] = incl;
}

__global__ void scan2_kernel(int* __restrict__ bsum, int nb) {
    __shared__ int s[64];
    int tid = threadIdx.x;
    s[tid] = (tid < nb) ? bsum[tid] : 0;
    __syncthreads();
    if (tid == 0) {
        int acc = 0;
        for (int i = 0; i < nb; i++) { int t = s[i]; s[i] = acc; acc += t; }
    }
    __syncthreads();
    if (tid < nb) bsum[tid] = s[tid];
}

__global__ void scan3_kernel(int* __restrict__ rowptr, const int* __restrict__ bsum, int n) {
    int idx = blockIdx.x * blockDim.x + threadIdx.x;
    if (idx == 0) rowptr[0] = 0;
    if (idx < n) rowptr[idx + 1] += bsum[idx >> 10];
}

__global__ void scatter_kernel(const int* __restrict__ src, const int* __restrict__ dst,
                               const int* __restrict__ rowptr, int* __restrict__ cnt,
                               int* __restrict__ colsrc, int E) {
    for (int e = blockIdx.x * blockDim.x + threadIdx.x; e < E; e += gridDim.x * blockDim.x) {
        int d = dst[e];
        int pos = atomicSub(&cnt[d], 1);
        colsrc[rowptr[d] + pos - 1] = src[e];
    }
}

// ---------------- fp16 split-MMA GEMM, fp32 A (layer 1) + fused el/er ----------------
// B fragments via ldmatrix.x4 (2 j's per op). Row stride 80B -> conflict-free LDSM.
__global__ __launch_bounds__(256, 3) void mma_gemm_f16_kernel(
    const float* __restrict__ A,
    const __half* __restrict__ Bth, const __half* __restrict__ Btl,
    float* __restrict__ C,
    const float* __restrict__ attn_l, const float* __restrict__ attn_r,
    float* __restrict__ el, float* __restrict__ er,
    int M, int Nc)
{
    const int BM = 128, BN = 64, BK = 32, K = 256;
    const int ASTR = 40;
    const int BSTR2 = 20;
    extern __shared__ float sm[];
    float*   As  = sm;                                    // [2][BM][40] f32
    __half2* Bh2 = (__half2*)(As + 2 * BM * ASTR);        // [2][BN][20] half2 hi
    __half2* Bl2 = Bh2 + 2 * BN * BSTR2;                  // [2][BN][20] half2 lo

    uint32_t as_b = smem_u32(As);
    uint32_t bh_b = smem_u32(Bh2);
    uint32_t bl_b = smem_u32(Bl2);

    int tid = threadIdx.x, lane = tid & 31, warp = tid >> 5;
    int blockRow = blockIdx.y * BM;
    int blockCol = blockIdx.x * BN;
    int g = lane >> 2, q = lane & 3;
    int lm = lane >> 3, lr = lane & 7;   // ldmatrix: matrix id / row id
    // B x4 matrices: m0=(j0,klo) m1=(j0,khi) m2=(j1,klo) m3=(j1,khi)
    uint32_t b_lane_off = (uint32_t)((((lm >> 1) * 8 + lr) * 80) + (lm & 1) * 16);

    float acc[8][4];
    #pragma unroll
    for (int j = 0; j < 8; j++)
        #pragma unroll
        for (int c = 0; c < 4; c++) acc[j][c] = 0.f;

    auto load_tile = [&](int t) {
        int buf = t & 1, k0 = t * BK;
        #pragma unroll
        for (int l = 0; l < 4; l++) {
            int c = tid + l * 256;
            int r = c >> 3, kq = (c & 7) * 4;
            const float* gp = A + (size_t)(blockRow + r) * K + k0 + kq;
            uint32_t sa = as_b + (uint32_t)(((buf * BM + r) * ASTR + kq) * 4);
            uint32_t sz = (blockRow + r < M) ? 16u : 0u;
            CP_ASYNC16_Z(sa, gp, sz);
        }
        {
            int n = tid >> 2, ch = tid & 3;
            size_t go = (size_t)(blockCol + n) * K + k0 + ch * 8;
            uint32_t so = (uint32_t)(((buf * BN + n) * BSTR2 + ch * 4) * 4);
            CP_ASYNC16(bh_b + so, Bth + go);
            CP_ASYNC16(bl_b + so, Btl + go);
        }
        CP_COMMIT();
    };

    load_tile(0);

    #pragma unroll 1
    for (int t = 0; t < K / BK; t++) {
        if (t < K / BK - 1) {
            load_tile(t + 1);
            CP_WAIT(1);
        } else {
            CP_WAIT(0);
        }
        __syncthreads();

        int buf = t & 1;
        const float2* Af2 = (const float2*)(As + buf * BM * ASTR);
        uint32_t bh_buf = bh_b + (uint32_t)(buf * 5120) + b_lane_off;
        uint32_t bl_buf = bl_b + (uint32_t)(buf * 5120) + b_lane_off;

        #pragma unroll
        for (int ks = 0; ks < 2; ks++) {
            int kof = ks * 8;
            int r0 = warp * 16 + g;
            uint32_t ah[4], al[4];
            float2 x00 = Af2[(r0    ) * 20 + kof + q];
            float2 x10 = Af2[(r0 + 8) * 20 + kof + q];
            float2 x01 = Af2[(r0    ) * 20 + kof + q + 4];
            float2 x11 = Af2[(r0 + 8) * 20 + kof + q + 4];
            split2(x00, ah[0], al[0]);
            split2(x10, ah[1], al[1]);
            split2(x01, ah[2], al[2]);
            split2(x11, ah[3], al[3]);
            #pragma unroll
            for (int p = 0; p < 4; p++) {
                uint32_t bh0, bh1, bh2_, bh3, bl0, bl1, bl2_, bl3;
                uint32_t off = (uint32_t)(p * 1280 + ks * 32);
                LDSM_X4(bh0, bh1, bh2_, bh3, bh_buf + off);
                LDSM_X4(bl0, bl1, bl2_, bl3, bl_buf + off);
                MMA_F16(acc[2 * p],     ah[0], ah[1], ah[2], ah[3], bh0, bh1);
                MMA_F16(acc[2 * p],     al[0], al[1], al[2], al[3], bh0, bh1);
                MMA_F16(acc[2 * p],     ah[0], ah[1], ah[2], ah[3], bl0, bl1);
                MMA_F16(acc[2 * p + 1], ah[0], ah[1], ah[2], ah[3], bh2_, bh3);
                MMA_F16(acc[2 * p + 1], al[0], al[1], al[2], al[3], bh2_, bh3);
                MMA_F16(acc[2 * p + 1], ah[0], ah[1], ah[2], ah[3], bl2_, bl3);
            }
        }
        __syncthreads();
    }

    // ---- store C (fp32) ----
    int r0 = blockRow + warp * 16 + g;
    int r1 = r0 + 8;
    #pragma unroll
    for (int j = 0; j < 8; j++) {
        int c = blockCol + j * 8 + q * 2;
        if (r0 < M) *(float2*)(C + (size_t)r0 * Nc + c) = make_float2(acc[j][0], acc[j][1]);
        if (r1 < M) *(float2*)(C + (size_t)r1 * Nc + c) = make_float2(acc[j][2], acc[j][3]);
    }

    // ---- fused el/er epilogue (head = blockIdx.x) ----
    float pl0 = 0.f, pl1 = 0.f, pr0 = 0.f, pr1 = 0.f;
    #pragma unroll
    for (int j = 0; j < 8; j++) {
        int idx = blockCol + j * 8 + q * 2;
        float a0 = __ldg(&attn_l[idx]), a1 = __ldg(&attn_l[idx + 1]);
        float b0 = __ldg(&attn_r[idx]), b1 = __ldg(&attn_r[idx + 1]);
        pl0 += acc[j][0] * a0 + acc[j][1] * a1;
        pl1 += acc[j][2] * a0 + acc[j][3] * a1;
        pr0 += acc[j][0] * b0 + acc[j][1] * b1;
        pr1 += acc[j][2] * b0 + acc[j][3] * b1;
    }
    #pragma unroll
    for (int off = 1; off <= 2; off <<= 1) {
        pl0 += __shfl_xor_sync(0xffffffffu, pl0, off);
        pl1 += __shfl_xor_sync(0xffffffffu, pl1, off);
        pr0 += __shfl_xor_sync(0xffffffffu, pr0, off);
        pr1 += __shfl_xor_sync(0xffffffffu, pr1, off);
    }
    if (q == 0) {
        if (r0 < M) {
            el[(size_t)r0 * 4 + blockIdx.x] = pl0;
            er[(size_t)r0 * 4 + blockIdx.x] = pr0;
        }
        if (r1 < M) {
            el[(size_t)r1 * 4 + blockIdx.x] = pl1;
            er[(size_t)r1 * 4 + blockIdx.x] = pr1;
        }
    }
}

// ---------------- fp16-A split-MMA GEMM (layer 2: A pre-split by agg1) ----------------
// A and B fragments via ldmatrix.x4. el/er combined via atomicAdd (pre-zeroed).
__global__ __launch_bounds__(256, 3) void mma_gemm_f16a_kernel(
    const __half* __restrict__ Ath, const __half* __restrict__ Atl,
    const __half* __restrict__ Bth, const __half* __restrict__ Btl,
    float* __restrict__ C,
    const float* __restrict__ attn_l, const float* __restrict__ attn_r,
    float* __restrict__ el, float* __restrict__ er,
    int M, int Nc)
{
    const int BM = 128, BN = 64, BK = 32, K = 256;
    const int STR2 = 20;
    extern __shared__ float sm[];
    __half2* Ah2 = (__half2*)sm;                  // [2][BM][20] hi
    __half2* Al2 = Ah2 + 2 * BM * STR2;           // [2][BM][20] lo
    __half2* Bh2 = Al2 + 2 * BM * STR2;           // [2][BN][20] hi
    __half2* Bl2 = Bh2 + 2 * BN * STR2;           // [2][BN][20] lo

    uint32_t ah_b = smem_u32(Ah2);
    uint32_t al_b = smem_u32(Al2);
    uint32_t bh_b = smem_u32(Bh2);
    uint32_t bl_b = smem_u32(Bl2);

    int tid = threadIdx.x, lane = tid & 31, warp = tid >> 5;
    int blockRow = blockIdx.y * BM;
    int blockCol = blockIdx.x * BN;
    int g = lane >> 2, q = lane & 3;
    int lm = lane >> 3, lr = lane & 7;
    // A x4 matrices: m0=(rows+0,klo) m1=(rows+8,klo) m2=(rows+0,khi) m3=(rows+8,khi)
    uint32_t a_lane_off = (uint32_t)((((lm & 1) * 8 + lr) * 80) + (lm >> 1) * 16);
    // B x4 matrices: m0=(j0,klo) m1=(j0,khi) m2=(j1,klo) m3=(j1,khi)
    uint32_t b_lane_off = (uint32_t)((((lm >> 1) * 8 + lr) * 80) + (lm & 1) * 16);

    float acc[8][4];
    #pragma unroll
    for (int j = 0; j < 8; j++)
        #pragma unroll
        for (int c = 0; c < 4; c++) acc[j][c] = 0.f;

    auto load_tile = [&](int t) {
        int buf = t & 1, k0 = t * BK;
        #pragma unroll
        for (int l = 0; l < 2; l++) {
            int c = tid + l * 256;
            int r = c >> 2, ch = c & 3;
            size_t go = (size_t)(blockRow + r) * K + k0 + ch * 8;
            uint32_t so = (uint32_t)(((buf * BM + r) * STR2 + ch * 4) * 4);
            uint32_t sz = (blockRow + r < M) ? 16u : 0u;
            CP_ASYNC16_Z(ah_b + so, Ath + go, sz);
            CP_ASYNC16_Z(al_b + so, Atl + go, sz);
        }
        {
            int n = tid >> 2, ch = tid & 3;
            size_t go = (size_t)(blockCol + n) * K + k0 + ch * 8;
            uint32_t so = (uint32_t)(((buf * BN + n) * STR2 + ch * 4) * 4);
            CP_ASYNC16(bh_b + so, Bth + go);
            CP_ASYNC16(bl_b + so, Btl + go);
        }
        CP_COMMIT();
    };

    load_tile(0);

    #pragma unroll 1
    for (int t = 0; t < K / BK; t++) {
        if (t < K / BK - 1) {
            load_tile(t + 1);
            CP_WAIT(1);
        } else {
            CP_WAIT(0);
        }
        __syncthreads();

        int buf = t & 1;
        uint32_t ah_buf = ah_b + (uint32_t)(buf * 10240 + warp * 1280) + a_lane_off;
        uint32_t al_buf = al_b + (uint32_t)(buf * 10240 + warp * 1280) + a_lane_off;
        uint32_t bh_buf = bh_b + (uint32_t)(buf * 5120) + b_lane_off;
        uint32_t bl_buf = bl_b + (uint32_t)(buf * 5120) + b_lane_off;

        #pragma unroll
        for (int ks = 0; ks < 2; ks++) {
            uint32_t koff = (uint32_t)(ks * 32);
            uint32_t ah[4], al[4];
            LDSM_X4(ah[0], ah[1], ah[2], ah[3], ah_buf + koff);
            LDSM_X4(al[0], al[1], al[2], al[3], al_buf + koff);
            #pragma unroll
            for (int p = 0; p < 4; p++) {
                uint32_t bh0, bh1, bh2_, bh3, bl0, bl1, bl2_, bl3;
                uint32_t off = (uint32_t)(p * 1280) + koff;
                LDSM_X4(bh0, bh1, bh2_, bh3, bh_buf + off);
                LDSM_X4(bl0, bl1, bl2_, bl3, bl_buf + off);
                MMA_F16(acc[2 * p],     ah[0], ah[1], ah[2], ah[3], bh0, bh1);
                MMA_F16(acc[2 * p],     al[0], al[1], al[2], al[3], bh0, bh1);
                MMA_F16(acc[2 * p],     ah[0], ah[1], ah[2], ah[3], bl0, bl1);
                MMA_F16(acc[2 * p + 1], ah[0], ah[1], ah[2], ah[3], bh2_, bh3);
                MMA_F16(acc[2 * p + 1], al[0], al[1], al[2], al[3], bh2_, bh3);
                MMA_F16(acc[2 * p + 1], ah[0], ah[1], ah[2], ah[3], bl2_, bl3);
            }
        }
        __syncthreads();
    }

    // ---- store C (fp32) ----
    int r0 = blockRow + warp * 16 + g;
    int r1 = r0 + 8;
    #pragma unroll
    for (int j = 0; j < 8; j++) {
        int c = blockCol + j * 8 + q * 2;
        if (r0 < M) *(float2*)(C + (size_t)r0 * Nc + c) = make_float2(acc[j][0], acc[j][1]);
        if (r1 < M) *(float2*)(C + (size_t)r1 * Nc + c) = make_float2(acc[j][2], acc[j][3]);
    }

    // ---- fused el/er epilogue: combined via atomicAdd (arrays pre-zeroed) ----
    float pl0 = 0.f, pl1 = 0.f, pr0 = 0.f, pr1 = 0.f;
    #pragma unroll
    for (int j = 0; j < 8; j++) {
        int idx = blockCol + j * 8 + q * 2;
        float a0 = __ldg(&attn_l[idx]), a1 = __ldg(&attn_l[idx + 1]);
        float b0 = __ldg(&attn_r[idx]), b1 = __ldg(&attn_r[idx + 1]);
        pl0 += acc[j][0] * a0 + acc[j][1] * a1;
        pl1 += acc[j][2] * a0 + acc[j][3] * a1;
        pr0 += acc[j][0] * b0 + acc[j][1] * b1;
        pr1 += acc[j][2] * b0 + acc[j][3] * b1;
    }
    #pragma unroll
    for (int off = 1; off <= 2; off <<= 1) {
        pl0 += __shfl_xor_sync(0xffffffffu, pl0, off);
        pl1 += __shfl_xor_sync(0xffffffffu, pl1, off);
        pr0 += __shfl_xor_sync(0xffffffffu, pr0, off);
        pr1 += __shfl_xor_sync(0xffffffffu, pr1, off);
    }
    if (q == 0) {
        if (r0 < M) { atomicAdd(&el[r0], pl0); atomicAdd(&er[r0], pr0); }
        if (r1 < M) { atomicAdd(&el[r1], pl1); atomicAdd(&er[r1], pr1); }
    }
}

// ---------------- fused softmax + aggregation ----------------
__device__ __forceinline__ float leaky_exp(float e) {
    e = (e > 0.f) ? e : NEG_SLOPE * e;
    return __expf(e);
}

// layer 1: H=4, D=64, C=256, fp32 features. One warp per node.
// Output h1 written directly as fp16 hi/lo split (consumed by gemm2's fp16-A path).
__global__ __launch_bounds__(256) void aggregate1_kernel(
    const float* __restrict__ ft, const float* __restrict__ el, const float* __restrict__ er,
    const int* __restrict__ rowptr, const int* __restrict__ colsrc,
    const float* __restrict__ bias, __half* __restrict__ outh, __half* __restrict__ outl, int Nn)
{
    int warp = threadIdx.x >> 5, lane = threadIdx.x & 31;
    int n = blockIdx.x * 8 + warp;
    if (n >= Nn) return;
    int start = rowptr[n];
    int deg = rowptr[n + 1] - start;

    const bool hlo = (lane < 16);
    float4 er4 = __ldg((const float4*)(er + (size_t)n * 4));
    float erA = hlo ? er4.x : er4.y;
    float erB = hlo ? er4.z : er4.w;

    float4 accA = make_float4(0.f, 0.f, 0.f, 0.f);
    float4 accB = make_float4(0.f, 0.f, 0.f, 0.f);
    float wsumA = 0.f, wsumB = 0.f;
    const float* ftA = ft + lane * 4;
    const float* ftB = ft + 128 + lane * 4;

    int k = 0;
    for (; k + 4 <= deg; k += 4) {
        int s0 = __ldg(&colsrc[start + k + 0]);
        int s1 = __ldg(&colsrc[start + k + 1]);
        int s2 = __ldg(&colsrc[start + k + 2]);
        int s3 = __ldg(&colsrc[start + k + 3]);
        float4 l0 = __ldg((const float4*)(el + (size_t)s0 * 4));
        float4 l1 = __ldg((const float4*)(el + (size_t)s1 * 4));
        float4 l2 = __ldg((const float4*)(el + (size_t)s2 * 4));
        float4 l3 = __ldg((const float4*)(el + (size_t)s3 * 4));
        float4 fA0 = *(const float4*)(ftA + (size_t)s0 * 256);
        float4 fB0 = *(const float4*)(ftB + (size_t)s0 * 256);
        float4 fA1 = *(const float4*)(ftA + (size_t)s1 * 256);
        float4 fB1 = *(const float4*)(ftB + (size_t)s1 * 256);
        float4 fA2 = *(const float4*)(ftA + (size_t)s2 * 256);
        float4 fB2 = *(const float4*)(ftB + (size_t)s2 * 256);
        float4 fA3 = *(const float4*)(ftA + (size_t)s3 * 256);
        float4 fB3 = *(const float4*)(ftB + (size_t)s3 * 256);
        float wA0 = leaky_exp((hlo ? l0.x : l0.y) + erA);
        float wB0 = leaky_exp((hlo ? l0.z : l0.w) + erB);
        float wA1 = leaky_exp((hlo ? l1.x : l1.y) + erA);
        float wB1 = leaky_exp((hlo ? l1.z : l1.w) + erB);
        float wA2 = leaky_exp((hlo ? l2.x : l2.y) + erA);
        float wB2 = leaky_exp((hlo ? l2.z : l2.w) + erB);
        float wA3 = leaky_exp((hlo ? l3.x : l3.y) + erA);
        float wB3 = leaky_exp((hlo ? l3.z : l3.w) + erB);
        accA.x += wA0 * fA0.x + wA1 * fA1.x + wA2 * fA2.x + wA3 * fA3.x;
        accA.y += wA0 * fA0.y + wA1 * fA1.y + wA2 * fA2.y + wA3 * fA3.y;
        accA.z += wA0 * fA0.z + wA1 * fA1.z + wA2 * fA2.z + wA3 * fA3.z;
        accA.w += wA0 * fA0.w + wA1 * fA1.w + wA2 * fA2.w + wA3 * fA3.w;
        accB.x += wB0 * fB0.x + wB1 * fB1.x + wB2 * fB2.x + wB3 * fB3.x;
        accB.y += wB0 * fB0.y + wB1 * fB1.y + wB2 * fB2.y + wB3 * fB3.y;
        accB.z += wB0 * fB0.z + wB1 * fB1.z + wB2 * fB2.z + wB3 * fB3.z;
        accB.w += wB0 * fB0.w + wB1 * fB1.w + wB2 * fB2.w + wB3 * fB3.w;
        wsumA += (wA0 + wA1) + (wA2 + wA3);
        wsumB += (wB0 + wB1) + (wB2 + wB3);
    }
    for (; k < deg; k++) {
        int s0 = __ldg(&colsrc[start + k]);
        float4 l0 = __ldg((const float4*)(el + (size_t)s0 * 4));
        float4 fA0 = *(const float4*)(ftA + (size_t)s0 * 256);
        float4 fB0 = *(const float4*)(ftB + (size_t)s0 * 256);
        float wA0 = leaky_exp((hlo ? l0.x : l0.y) + erA);
        float wB0 = leaky_exp((hlo ? l0.z : l0.w) + erB);
        accA.x += wA0 * fA0.x; accA.y += wA0 * fA0.y;
        accA.z += wA0 * fA0.z; accA.w += wA0 * fA0.w;
        accB.x += wB0 * fB0.x; accB.y += wB0 * fB0.y;
        accB.z += wB0 * fB0.z; accB.w += wB0 * fB0.w;
        wsumA += wA0; wsumB += wB0;
    }

    float invA = (deg > 0) ? (1.f / wsumA) : 0.f;
    float invB = (deg > 0) ? (1.f / wsumB) : 0.f;
    float4 bA = __ldg((const float4*)(bias + lane * 4));
    float4 bB = __ldg((const float4*)(bias + 128 + lane * 4));
    float4 oA, oB;
    oA.x = fmaxf(accA.x * invA + bA.x, 0.f);
    oA.y = fmaxf(accA.y * invA + bA.y, 0.f);
    oA.z = fmaxf(accA.z * invA + bA.z, 0.f);
    oA.w = fmaxf(accA.w * invA + bA.w, 0.f);
    oB.x = fmaxf(accB.x * invB + bB.x, 0.f);
    oB.y = fmaxf(accB.y * invB + bB.y, 0.f);
    oB.z = fmaxf(accB.z * invB + bB.z, 0.f);
    oB.w = fmaxf(accB.w * invB + bB.w, 0.f);

    uint32_t hA0, lA0, hA1, lA1, hB0, lB0, hB1, lB1;
    split2(make_float2(oA.x, oA.y), hA0, lA0);
    split2(make_float2(oA.z, oA.w), hA1, lA1);
    split2(make_float2(oB.x, oB.y), hB0, lB0);
    split2(make_float2(oB.z, oB.w), hB1, lB1);
    *(uint2*)(outh + (size_t)n * 256 + lane * 4)       = make_uint2(hA0, hA1);
    *(uint2*)(outl + (size_t)n * 256 + lane * 4)       = make_uint2(lA0, lA1);
    *(uint2*)(outh + (size_t)n * 256 + 128 + lane * 4) = make_uint2(hB0, hB1);
    *(uint2*)(outl + (size_t)n * 256 + 128 + lane * 4) = make_uint2(lB0, lB1);
}

// layer 2: H=1, D=128, fp32 features. Combined el/er arrays.
__global__ __launch_bounds__(256) void aggregate2_kernel(
    const float* __restrict__ ft, const float* __restrict__ el, const float* __restrict__ er,
    const int* __restrict__ rowptr, const int* __restrict__ colsrc,
    const float* __restrict__ bias, float* __restrict__ out, int Nn)
{
    int warp = threadIdx.x >> 5, lane = threadIdx.x & 31;
    int n = blockIdx.x * 8 + warp;
    if (n >= Nn) return;
    int start = rowptr[n];
    int deg = rowptr[n + 1] - start;

    float er_n = __ldg(&er[n]);
    float4 acc = make_float4(0.f, 0.f, 0.f, 0.f);
    float wsum = 0.f;
    const float* ftp = ft + lane * 4;

    int k = 0;
    for (; k + 8 <= deg; k += 8) {
        int s[8];
        #pragma unroll
        for (int u = 0; u < 8; u++) s[u] = __ldg(&colsrc[start + k + u]);
        float e[8];
        #pragma unroll
        for (int u = 0; u < 8; u++) e[u] = __ldg(&el[s[u]]);
        float4 f[8];
        #pragma unroll
        for (int u = 0; u < 8; u++) f[u] = *(const float4*)(ftp + (size_t)s[u] * 128);
        #pragma unroll
        for (int u = 0; u < 8; u++) {
            float w = leaky_exp(e[u] + er_n);
            acc.x += w * f[u].x; acc.y += w * f[u].y;
            acc.z += w * f[u].z; acc.w += w * f[u].w;
            wsum += w;
        }
    }
    for (; k < deg; k++) {
        int s0 = __ldg(&colsrc[start + k]);
        float w = leaky_exp(__ldg(&el[s0]) + er_n);
        float4 f0 = *(const float4*)(ftp + (size_t)s0 * 128);
        acc.x += w * f0.x; acc.y += w * f0.y;
        acc.z += w * f0.z; acc.w += w * f0.w;
        wsum += w;
    }

    float inv = (deg > 0) ? (1.f / wsum) : 0.f;
    float4 b = __ldg((const float4*)(bias + lane * 4));
    float4 o;
    o.x = acc.x * inv + b.x;
    o.y = acc.y * inv + b.y;
    o.z = acc.z * inv + b.z;
    o.w = acc.w * inv + b.w;
    *(float4*)(out + (size_t)n * 128 + lane * 4) = o;
}

// ---------------- launch (single stream) ----------------
extern "C" void kernel_launch(void* const* d_in, const int* in_sizes, int n_in,
                              void* d_out, int out_size)
{
    const float* feat    = (const float*)d_in[0];
    const int*   src     = (const int*)  d_in[1];
    const int*   dst     = (const int*)  d_in[2];
    const float* W1      = (const float*)d_in[3];
    const float* attn_l1 = (const float*)d_in[4];
    const float* attn_r1 = (const float*)d_in[5];
    const float* bias1   = (const float*)d_in[6];
    const float* W2      = (const float*)d_in[7];
    const float* attn_l2 = (const float*)d_in[8];
    const float* attn_r2 = (const float*)d_in[9];
    const float* bias2   = (const float*)d_in[10];
    float* out = (float*)d_out;

    float *ft1, *el1, *er1, *ft2, *el2, *er2;
    __half *h1h, *h1l, *wt1h, *wt1l, *wt2h, *wt2l;
    int *cnt, *rowptr, *colsrc, *bsum;
    cudaGetSymbolAddress((void**)&ft1,    g_ft1);
    cudaGetSymbolAddress((void**)&h1h,    g_h1h);
    cudaGetSymbolAddress((void**)&h1l,    g_h1l);
    cudaGetSymbolAddress((void**)&el1,    g_el1);
    cudaGetSymbolAddress((void**)&er1,    g_er1);
    cudaGetSymbolAddress((void**)&ft2,    g_ft2);
    cudaGetSymbolAddress((void**)&el2,    g_el2);
    cudaGetSymbolAddress((void**)&er2,    g_er2);
    cudaGetSymbolAddress((void**)&wt1h,   g_wt1h);
    cudaGetSymbolAddress((void**)&wt1l,   g_wt1l);
    cudaGetSymbolAddress((void**)&wt2h,   g_wt2h);
    cudaGetSymbolAddress((void**)&wt2l,   g_wt2l);
    cudaGetSymbolAddress((void**)&cnt,    g_cnt);
    cudaGetSymbolAddress((void**)&rowptr, g_rowptr);
    cudaGetSymbolAddress((void**)&colsrc, g_colsrc);
    cudaGetSymbolAddress((void**)&bsum,   g_bsum);

    const int SMEM_SZ  = (2 * 128 * 40) * 4 + (2 * 2 * 64 * 20) * 4;                 // 61440
    const int SMEM_SZA = (2 * 2 * 128 * 20) * 4 + (2 * 2 * 64 * 20) * 4;             // 61440
    cudaFuncSetAttribute(mma_gemm_f16_kernel,  cudaFuncAttributeMaxDynamicSharedMemorySize, SMEM_SZ);
    cudaFuncSetAttribute(mma_gemm_f16a_kernel, cudaFuncAttributeMaxDynamicSharedMemorySize, SMEM_SZA);

    transpose_split_kernel<<<384, 256>>>(W1, W2, wt1h, wt1l, wt2h, wt2l, cnt, el2, er2); // 1
    count_dst_kernel<<<2048, 256>>>(dst, cnt, N_EDGES);                            // 2
    scan1_kernel<<<SCAN_NB, 1024>>>(cnt, rowptr, bsum, N_NODES);                   // 3
    {                                                                              // 4: gemm1 (profiled)
        dim3 grid(4, (N_NODES + 127) / 128);
        mma_gemm_f16_kernel<<<grid, 256, SMEM_SZ>>>(feat, wt1h, wt1l, ft1,
                                                    attn_l1, attn_r1, el1, er1,
                                                    N_NODES, 256);
    }
    scan2_kernel<<<1, 64>>>(bsum, SCAN_NB);                                        // 5
    scan3_kernel<<<(N_NODES + 255) / 256, 256>>>(rowptr, bsum, N_NODES);           // 6
    scatter_kernel<<<2048, 256>>>(src, dst, rowptr, cnt, colsrc, N_EDGES);         // 7
    aggregate1_kernel<<<(N_NODES + 7) / 8, 256>>>(ft1, el1, er1, rowptr, colsrc,   // 8
                                                  bias1, h1h, h1l, N_NODES);
    {                                                                              // 9: gemm2 (fp16 A)
        dim3 grid(2, (N_NODES + 127) / 128);
        mma_gemm_f16a_kernel<<<grid, 256, SMEM_SZA>>>(h1h, h1l, wt2h, wt2l, ft2,
                                                      attn_l2, attn_r2, el2, er2,
                                                      N_NODES, 128);
    }
    aggregate2_kernel<<<(N_NODES + 7) / 8, 256>>>(ft2, el2, er2, rowptr, colsrc,   // 10
                                                  bias2, out, N_NODES);
}

// round 15
// speedup vs baseline: 1.3235x; 1.1078x over previous
#include <cuda_runtime.h>
#include <cuda_fp16.h>
#include <math.h>
#include <stdint.h>

#define N_NODES 50000
#define N_EDGES 800000
#define NEG_SLOPE 0.2f
#define SCAN_NB ((N_NODES + 1023) / 1024)   // 49

// ---------------- scratch (device globals; no allocation allowed) ----------------
__device__ float  g_ft1[N_NODES * 256];
__device__ __half g_h1h[N_NODES * 256];    // layer-1 output, fp16 hi
__device__ __half g_h1l[N_NODES * 256];    // layer-1 output, fp16 lo (residual)
__device__ float  g_el1[N_NODES * 4];
__device__ float  g_er1[N_NODES * 4];
__device__ float  g_ft2[N_NODES * 128];
__device__ float  g_el2[N_NODES];
__device__ float  g_er2[N_NODES];
__device__ int    g_cnt[N_NODES];
__device__ int    g_rowptr[N_NODES + 1];
__device__ int    g_bsum[64];
__device__ int    g_colsrc[N_EDGES];
__device__ __half g_wt1h[256 * 256];   // W1^T fp16 [n][k]
__device__ __half g_wt2h[128 * 256];   // W2^T fp16

// ---------------- helpers ----------------
__device__ __forceinline__ uint32_t smem_u32(const void* p) {
    uint32_t a;
    asm("{ .reg .u64 t; cvta.to.shared.u64 t, %1; cvt.u32.u64 %0, t; }" : "=r"(a) : "l"(p));
    return a;
}

#define CP_ASYNC16(sa, gp) \
    asm volatile("cp.async.cg.shared.global [%0], [%1], 16;" :: "r"(sa), "l"(gp) : "memory")
#define CP_ASYNC16_Z(sa, gp, sz) \
    asm volatile("cp.async.cg.shared.global [%0], [%1], 16, %2;" :: "r"(sa), "l"(gp), "r"(sz) : "memory")
#define CP_COMMIT()  asm volatile("cp.async.commit_group;" ::: "memory")
#define CP_WAIT(n)   asm volatile("cp.async.wait_group %0;" :: "n"(n) : "memory")

#define MMA_F16(d, a0, a1, a2, a3, b0, b1)                                    \
    asm volatile("mma.sync.aligned.m16n8k16.row.col.f32.f16.f16.f32 "         \
                 "{%0,%1,%2,%3}, {%4,%5,%6,%7}, {%8,%9}, {%0,%1,%2,%3};"      \
                 : "+f"(d[0]), "+f"(d[1]), "+f"(d[2]), "+f"(d[3])             \
                 : "r"(a0), "r"(a1), "r"(a2), "r"(a3), "r"(b0), "r"(b1))

#define LDSM_X4(r0, r1, r2, r3, addr)                                         \
    asm volatile("ldmatrix.sync.aligned.m8n8.x4.shared.b16 {%0,%1,%2,%3}, [%4];" \
                 : "=r"(r0), "=r"(r1), "=r"(r2), "=r"(r3) : "r"(addr))

// split a float2 into packed fp16 hi + fp16 residual lo
__device__ __forceinline__ void split2(float2 x, uint32_t& h, uint32_t& l) {
    __half2 hh = __floats2half2_rn(x.x, x.y);
    float2 hf = __half22float2(hh);
    __half2 ll = __floats2half2_rn(x.x - hf.x, x.y - hf.y);
    h = *reinterpret_cast<uint32_t*>(&hh);
    l = *reinterpret_cast<uint32_t*>(&ll);
}

// ---------------- small utils ----------------
__global__ void count_dst_kernel(const int* __restrict__ dst, int* __restrict__ cnt, int E) {
    for (int e = blockIdx.x * blockDim.x + threadIdx.x; e < E; e += gridDim.x * blockDim.x)
        atomicAdd(&cnt[dst[e]], 1);
}

// transpose + fp16 convert of both weight matrices; zeroes cnt[] and el2/er2
__global__ void transpose_split_kernel(const float* __restrict__ W1, const float* __restrict__ W2,
                                       __half* __restrict__ t1h, __half* __restrict__ t2h,
                                       int* __restrict__ cnt,
                                       float* __restrict__ el2, float* __restrict__ er2) {
    int t = blockIdx.x * blockDim.x + threadIdx.x;
    if (t < N_NODES) { cnt[t] = 0; el2[t] = 0.f; er2[t] = 0.f; }
    if (t < 65536) {
        int k = t & 255, n = t >> 8;
        t1h[n * 256 + k] = __float2half_rn(W1[k * 256 + n]);
    } else if (t < 98304) {
        int u = t - 65536;
        int k = u & 255, n = u >> 8;
        t2h[n * 256 + k] = __float2half_rn(W2[k * 128 + n]);
    }
}

// ---- parallel 3-phase scan ----
__global__ __launch_bounds__(1024) void scan1_kernel(const int* __restrict__ cnt,
                                                     int* __restrict__ rowptr,
                                                     int* __restrict__ bsum, int n) {
    __shared__ int warp_sums[32];
    int tid = threadIdx.x, lane = tid & 31, warp = tid >> 5;
    int idx = blockIdx.x * 1024 + tid;
    int v = (idx < n) ? cnt[idx] : 0;
    int x = v;
    #pragma unroll
    for (int off = 1; off < 32; off <<= 1) {
        int y = __shfl_up_sync(0xffffffffu, x, off);
        if (lane >= off) x += y;
    }
    if (lane == 31) warp_sums[warp] = x;
    __syncthreads();
    if (warp == 0) {
        int s = warp_sums[lane];
        #pragma unroll
        for (int off = 1; off < 32; off <<= 1) {
            int y = __shfl_up_sync(0xffffffffu, s, off);
            if (lane >= off) s += y;
        }
        warp_sums[lane] = s;
    }
    __syncthreads();
    int incl = x + ((warp > 0) ? warp_sums[warp - 1] : 0);
    if (idx < n) rowptr[idx + 1] = incl;
    if (tid == 1023) bsum[blockIdx.x] = incl;
}

__global__ void scan2_kernel(int* __restrict__ bsum, int nb) {
    __shared__ int s[64];
    int tid = threadIdx.x;
    s[tid] = (tid < nb) ? bsum[tid] : 0;
    __syncthreads();
    if (tid == 0) {
        int acc = 0;
        for (int i = 0; i < nb; i++) { int t = s[i]; s[i] = acc; acc += t; }
    }
    __syncthreads();
    if (tid < nb) bsum[tid] = s[tid];
}

__global__ void scan3_kernel(int* __restrict__ rowptr, const int* __restrict__ bsum, int n) {
    int idx = blockIdx.x * blockDim.x + threadIdx.x;
    if (idx == 0) rowptr[0] = 0;
    if (idx < n) rowptr[idx + 1] += bsum[idx >> 10];
}

__global__ void scatter_kernel(const int* __restrict__ src, const int* __restrict__ dst,
                               const int* __restrict__ rowptr, int* __restrict__ cnt,
                               int* __restrict__ colsrc, int E) {
    for (int e = blockIdx.x * blockDim.x + threadIdx.x; e < E; e += gridDim.x * blockDim.x) {
        int d = dst[e];
        int pos = atomicSub(&cnt[d], 1);
        colsrc[rowptr[d] + pos - 1] = src[e];
    }
}

// ---------------- fp16 A-split MMA GEMM, fp32 A (layer 1) + fused el/er ----------------
// A split hi+lo at fragment load; B single fp16. 2 MMAs per (j, k16).
__global__ __launch_bounds__(256, 3) void mma_gemm_f16_kernel(
    const float* __restrict__ A,
    const __half* __restrict__ Bth,
    float* __restrict__ C,
    const float* __restrict__ attn_l, const float* __restrict__ attn_r,
    float* __restrict__ el, float* __restrict__ er,
    int M, int Nc)
{
    const int BM = 128, BN = 64, BK = 32, K = 256;
    const int ASTR = 40;
    const int BSTR2 = 20;
    extern __shared__ float sm[];
    float*   As  = sm;                                    // [2][BM][40] f32
    __half2* Bh2 = (__half2*)(As + 2 * BM * ASTR);        // [2][BN][20] half2

    uint32_t as_b = smem_u32(As);
    uint32_t bh_b = smem_u32(Bh2);

    int tid = threadIdx.x, lane = tid & 31, warp = tid >> 5;
    int blockRow = blockIdx.y * BM;
    int blockCol = blockIdx.x * BN;
    int g = lane >> 2, q = lane & 3;
    int lm = lane >> 3, lr = lane & 7;
    // B x4 matrices: m0=(j0,klo) m1=(j0,khi) m2=(j1,klo) m3=(j1,khi)
    uint32_t b_lane_off = (uint32_t)((((lm >> 1) * 8 + lr) * 80) + (lm & 1) * 16);

    float acc[8][4];
    #pragma unroll
    for (int j = 0; j < 8; j++)
        #pragma unroll
        for (int c = 0; c < 4; c++) acc[j][c] = 0.f;

    auto load_tile = [&](int t) {
        int buf = t & 1, k0 = t * BK;
        #pragma unroll
        for (int l = 0; l < 4; l++) {
            int c = tid + l * 256;
            int r = c >> 3, kq = (c & 7) * 4;
            const float* gp = A + (size_t)(blockRow + r) * K + k0 + kq;
            uint32_t sa = as_b + (uint32_t)(((buf * BM + r) * ASTR + kq) * 4);
            uint32_t sz = (blockRow + r < M) ? 16u : 0u;
            CP_ASYNC16_Z(sa, gp, sz);
        }
        if (tid < 256) {
            int n = tid >> 2, ch = tid & 3;
            size_t go = (size_t)(blockCol + n) * K + k0 + ch * 8;
            uint32_t so = (uint32_t)(((buf * BN + n) * BSTR2 + ch * 4) * 4);
            CP_ASYNC16(bh_b + so, Bth + go);
        }
        CP_COMMIT();
    };

    load_tile(0);

    #pragma unroll 1
    for (int t = 0; t < K / BK; t++) {
        if (t < K / BK - 1) {
            load_tile(t + 1);
            CP_WAIT(1);
        } else {
            CP_WAIT(0);
        }
        __syncthreads();

        int buf = t & 1;
        const float2* Af2 = (const float2*)(As + buf * BM * ASTR);
        uint32_t bh_buf = bh_b + (uint32_t)(buf * 5120) + b_lane_off;

        #pragma unroll
        for (int ks = 0; ks < 2; ks++) {
            int kof = ks * 8;
            int r0 = warp * 16 + g;
            uint32_t ah[4], al[4];
            float2 x00 = Af2[(r0    ) * 20 + kof + q];
            float2 x10 = Af2[(r0 + 8) * 20 + kof + q];
            float2 x01 = Af2[(r0    ) * 20 + kof + q + 4];
            float2 x11 = Af2[(r0 + 8) * 20 + kof + q + 4];
            split2(x00, ah[0], al[0]);
            split2(x10, ah[1], al[1]);
            split2(x01, ah[2], al[2]);
            split2(x11, ah[3], al[3]);
            #pragma unroll
            for (int p = 0; p < 4; p++) {
                uint32_t bh0, bh1, bh2_, bh3;
                uint32_t off = (uint32_t)(p * 1280 + ks * 32);
                LDSM_X4(bh0, bh1, bh2_, bh3, bh_buf + off);
                MMA_F16(acc[2 * p],     ah[0], ah[1], ah[2], ah[3], bh0, bh1);
                MMA_F16(acc[2 * p],     al[0], al[1], al[2], al[3], bh0, bh1);
                MMA_F16(acc[2 * p + 1], ah[0], ah[1], ah[2], ah[3], bh2_, bh3);
                MMA_F16(acc[2 * p + 1], al[0], al[1], al[2], al[3], bh2_, bh3);
            }
        }
        __syncthreads();
    }

    // ---- store C (fp32) ----
    int r0 = blockRow + warp * 16 + g;
    int r1 = r0 + 8;
    #pragma unroll
    for (int j = 0; j < 8; j++) {
        int c = blockCol + j * 8 + q * 2;
        if (r0 < M) *(float2*)(C + (size_t)r0 * Nc + c) = make_float2(acc[j][0], acc[j][1]);
        if (r1 < M) *(float2*)(C + (size_t)r1 * Nc + c) = make_float2(acc[j][2], acc[j][3]);
    }

    // ---- fused el/er epilogue (head = blockIdx.x) ----
    float pl0 = 0.f, pl1 = 0.f, pr0 = 0.f, pr1 = 0.f;
    #pragma unroll
    for (int j = 0; j < 8; j++) {
        int idx = blockCol + j * 8 + q * 2;
        float a0 = __ldg(&attn_l[idx]), a1 = __ldg(&attn_l[idx + 1]);
        float b0 = __ldg(&attn_r[idx]), b1 = __ldg(&attn_r[idx + 1]);
        pl0 += acc[j][0] * a0 + acc[j][1] * a1;
        pl1 += acc[j][2] * a0 + acc[j][3] * a1;
        pr0 += acc[j][0] * b0 + acc[j][1] * b1;
        pr1 += acc[j][2] * b0 + acc[j][3] * b1;
    }
    #pragma unroll
    for (int off = 1; off <= 2; off <<= 1) {
        pl0 += __shfl_xor_sync(0xffffffffu, pl0, off);
        pl1 += __shfl_xor_sync(0xffffffffu, pl1, off);
        pr0 += __shfl_xor_sync(0xffffffffu, pr0, off);
        pr1 += __shfl_xor_sync(0xffffffffu, pr1, off);
    }
    if (q == 0) {
        if (r0 < M) {
            el[(size_t)r0 * 4 + blockIdx.x] = pl0;
            er[(size_t)r0 * 4 + blockIdx.x] = pr0;
        }
        if (r1 < M) {
            el[(size_t)r1 * 4 + blockIdx.x] = pl1;
            er[(size_t)r1 * 4 + blockIdx.x] = pr1;
        }
    }
}

// ---------------- fp16-A split MMA GEMM (layer 2: A pre-split, B single fp16) ----------------
__global__ __launch_bounds__(256, 3) void mma_gemm_f16a_kernel(
    const __half* __restrict__ Ath, const __half* __restrict__ Atl,
    const __half* __restrict__ Bth,
    float* __restrict__ C,
    const float* __restrict__ attn_l, const float* __restrict__ attn_r,
    float* __restrict__ el, float* __restrict__ er,
    int M, int Nc)
{
    const int BM = 128, BN = 64, BK = 32, K = 256;
    const int STR2 = 20;
    extern __shared__ float sm[];
    __half2* Ah2 = (__half2*)sm;                  // [2][BM][20] hi
    __half2* Al2 = Ah2 + 2 * BM * STR2;           // [2][BM][20] lo
    __half2* Bh2 = Al2 + 2 * BM * STR2;           // [2][BN][20]

    uint32_t ah_b = smem_u32(Ah2);
    uint32_t al_b = smem_u32(Al2);
    uint32_t bh_b = smem_u32(Bh2);

    int tid = threadIdx.x, lane = tid & 31, warp = tid >> 5;
    int blockRow = blockIdx.y * BM;
    int blockCol = blockIdx.x * BN;
    int g = lane >> 2, q = lane & 3;
    int lm = lane >> 3, lr = lane & 7;
    uint32_t a_lane_off = (uint32_t)((((lm & 1) * 8 + lr) * 80) + (lm >> 1) * 16);
    uint32_t b_lane_off = (uint32_t)((((lm >> 1) * 8 + lr) * 80) + (lm & 1) * 16);

    float acc[8][4];
    #pragma unroll
    for (int j = 0; j < 8; j++)
        #pragma unroll
        for (int c = 0; c < 4; c++) acc[j][c] = 0.f;

    auto load_tile = [&](int t) {
        int buf = t & 1, k0 = t * BK;
        #pragma unroll
        for (int l = 0; l < 2; l++) {
            int c = tid + l * 256;
            int r = c >> 2, ch = c & 3;
            size_t go = (size_t)(blockRow + r) * K + k0 + ch * 8;
            uint32_t so = (uint32_t)(((buf * BM + r) * STR2 + ch * 4) * 4);
            uint32_t sz = (blockRow + r < M) ? 16u : 0u;
            CP_ASYNC16_Z(ah_b + so, Ath + go, sz);
            CP_ASYNC16_Z(al_b + so, Atl + go, sz);
        }
        {
            int n = tid >> 2, ch = tid & 3;
            size_t go = (size_t)(blockCol + n) * K + k0 + ch * 8;
            uint32_t so = (uint32_t)(((buf * BN + n) * STR2 + ch * 4) * 4);
            CP_ASYNC16(bh_b + so, Bth + go);
        }
        CP_COMMIT();
    };

    load_tile(0);

    #pragma unroll 1
    for (int t = 0; t < K / BK; t++) {
        if (t < K / BK - 1) {
            load_tile(t + 1);
            CP_WAIT(1);
        } else {
            CP_WAIT(0);
        }
        __syncthreads();

        int buf = t & 1;
        uint32_t ah_buf = ah_b + (uint32_t)(buf * 10240 + warp * 1280) + a_lane_off;
        uint32_t al_buf = al_b + (uint32_t)(buf * 10240 + warp * 1280) + a_lane_off;
        uint32_t bh_buf = bh_b + (uint32_t)(buf * 5120) + b_lane_off;

        #pragma unroll
        for (int ks = 0; ks < 2; ks++) {
            uint32_t koff = (uint32_t)(ks * 32);
            uint32_t ah[4], al[4];
            LDSM_X4(ah[0], ah[1], ah[2], ah[3], ah_buf + koff);
            LDSM_X4(al[0], al[1], al[2], al[3], al_buf + koff);
            #pragma unroll
            for (int p = 0; p < 4; p++) {
                uint32_t bh0, bh1, bh2_, bh3;
                uint32_t off = (uint32_t)(p * 1280) + koff;
                LDSM_X4(bh0, bh1, bh2_, bh3, bh_buf + off);
                MMA_F16(acc[2 * p],     ah[0], ah[1], ah[2], ah[3], bh0, bh1);
                MMA_F16(acc[2 * p],     al[0], al[1], al[2], al[3], bh0, bh1);
                MMA_F16(acc[2 * p + 1], ah[0], ah[1], ah[2], ah[3], bh2_, bh3);
                MMA_F16(acc[2 * p + 1], al[0], al[1], al[2], al[3], bh2_, bh3);
            }
        }
        __syncthreads();
    }

    // ---- store C (fp32) ----
    int r0 = blockRow + warp * 16 + g;
    int r1 = r0 + 8;
    #pragma unroll
    for (int j = 0; j < 8; j++) {
        int c = blockCol + j * 8 + q * 2;
        if (r0 < M) *(float2*)(C + (size_t)r0 * Nc + c) = make_float2(acc[j][0], acc[j][1]);
        if (r1 < M) *(float2*)(C + (size_t)r1 * Nc + c) = make_float2(acc[j][2], acc[j][3]);
    }

    // ---- fused el/er epilogue: combined via atomicAdd (arrays pre-zeroed) ----
    float pl0 = 0.f, pl1 = 0.f, pr0 = 0.f, pr1 = 0.f;
    #pragma unroll
    for (int j = 0; j < 8; j++) {
        int idx = blockCol + j * 8 + q * 2;
        float a0 = __ldg(&attn_l[idx]), a1 = __ldg(&attn_l[idx + 1]);
        float b0 = __ldg(&attn_r[idx]), b1 = __ldg(&attn_r[idx + 1]);
        pl0 += acc[j][0] * a0 + acc[j][1] * a1;
        pl1 += acc[j][2] * a0 + acc[j][3] * a1;
        pr0 += acc[j][0] * b0 + acc[j][1] * b1;
        pr1 += acc[j][2] * b0 + acc[j][3] * b1;
    }
    #pragma unroll
    for (int off = 1; off <= 2; off <<= 1) {
        pl0 += __shfl_xor_sync(0xffffffffu, pl0, off);
        pl1 += __shfl_xor_sync(0xffffffffu, pl1, off);
        pr0 += __shfl_xor_sync(0xffffffffu, pr0, off);
        pr1 += __shfl_xor_sync(0xffffffffu, pr1, off);
    }
    if (q == 0) {
        if (r0 < M) { atomicAdd(&el[r0], pl0); atomicAdd(&er[r0], pr0); }
        if (r1 < M) { atomicAdd(&el[r1], pl1); atomicAdd(&er[r1], pr1); }
    }
}

// ---------------- fused softmax + aggregation ----------------
__device__ __forceinline__ float leaky_exp(float e) {
    e = (e > 0.f) ? e : NEG_SLOPE * e;
    return __expf(e);
}

// layer 1: H=4, D=64, C=256, fp32 features. One warp per node.
__global__ __launch_bounds__(256) void aggregate1_kernel(
    const float* __restrict__ ft, const float* __restrict__ el, const float* __restrict__ er,
    const int* __restrict__ rowptr, const int* __restrict__ colsrc,
    const float* __restrict__ bias, __half* __restrict__ outh, __half* __restrict__ outl, int Nn)
{
    int warp = threadIdx.x >> 5, lane = threadIdx.x & 31;
    int n = blockIdx.x * 8 + warp;
    if (n >= Nn) return;
    int start = rowptr[n];
    int deg = rowptr[n + 1] - start;

    const bool hlo = (lane < 16);
    float4 er4 = __ldg((const float4*)(er + (size_t)n * 4));
    float erA = hlo ? er4.x : er4.y;
    float erB = hlo ? er4.z : er4.w;

    float4 accA = make_float4(0.f, 0.f, 0.f, 0.f);
    float4 accB = make_float4(0.f, 0.f, 0.f, 0.f);
    float wsumA = 0.f, wsumB = 0.f;
    const float* ftA = ft + lane * 4;
    const float* ftB = ft + 128 + lane * 4;

    int k = 0;
    for (; k + 4 <= deg; k += 4) {
        int s0 = __ldg(&colsrc[start + k + 0]);
        int s1 = __ldg(&colsrc[start + k + 1]);
        int s2 = __ldg(&colsrc[start + k + 2]);
        int s3 = __ldg(&colsrc[start + k + 3]);
        float4 l0 = __ldg((const float4*)(el + (size_t)s0 * 4));
        float4 l1 = __ldg((const float4*)(el + (size_t)s1 * 4));
        float4 l2 = __ldg((const float4*)(el + (size_t)s2 * 4));
        float4 l3 = __ldg((const float4*)(el + (size_t)s3 * 4));
        float4 fA0 = *(const float4*)(ftA + (size_t)s0 * 256);
        float4 fB0 = *(const float4*)(ftB + (size_t)s0 * 256);
        float4 fA1 = *(const float4*)(ftA + (size_t)s1 * 256);
        float4 fB1 = *(const float4*)(ftB + (size_t)s1 * 256);
        float4 fA2 = *(const float4*)(ftA + (size_t)s2 * 256);
        float4 fB2 = *(const float4*)(ftB + (size_t)s2 * 256);
        float4 fA3 = *(const float4*)(ftA + (size_t)s3 * 256);
        float4 fB3 = *(const float4*)(ftB + (size_t)s3 * 256);
        float wA0 = leaky_exp((hlo ? l0.x : l0.y) + erA);
        float wB0 = leaky_exp((hlo ? l0.z : l0.w) + erB);
        float wA1 = leaky_exp((hlo ? l1.x : l1.y) + erA);
        float wB1 = leaky_exp((hlo ? l1.z : l1.w) + erB);
        float wA2 = leaky_exp((hlo ? l2.x : l2.y) + erA);
        float wB2 = leaky_exp((hlo ? l2.z : l2.w) + erB);
        float wA3 = leaky_exp((hlo ? l3.x : l3.y) + erA);
        float wB3 = leaky_exp((hlo ? l3.z : l3.w) + erB);
        accA.x += wA0 * fA0.x + wA1 * fA1.x + wA2 * fA2.x + wA3 * fA3.x;
        accA.y += wA0 * fA0.y + wA1 * fA1.y + wA2 * fA2.y + wA3 * fA3.y;
        accA.z += wA0 * fA0.z + wA1 * fA1.z + wA2 * fA2.z + wA3 * fA3.z;
        accA.w += wA0 * fA0.w + wA1 * fA1.w + wA2 * fA2.w + wA3 * fA3.w;
        accB.x += wB0 * fB0.x + wB1 * fB1.x + wB2 * fB2.x + wB3 * fB3.x;
        accB.y += wB0 * fB0.y + wB1 * fB1.y + wB2 * fB2.y + wB3 * fB3.y;
        accB.z += wB0 * fB0.z + wB1 * fB1.z + wB2 * fB2.z + wB3 * fB3.z;
        accB.w += wB0 * fB0.w + wB1 * fB1.w + wB2 * fB2.w + wB3 * fB3.w;
        wsumA += (wA0 + wA1) + (wA2 + wA3);
        wsumB += (wB0 + wB1) + (wB2 + wB3);
    }
    for (; k < deg; k++) {
        int s0 = __ldg(&colsrc[start + k]);
        float4 l0 = __ldg((const float4*)(el + (size_t)s0 * 4));
        float4 fA0 = *(const float4*)(ftA + (size_t)s0 * 256);
        float4 fB0 = *(const float4*)(ftB + (size_t)s0 * 256);
        float wA0 = leaky_exp((hlo ? l0.x : l0.y) + erA);
        float wB0 = leaky_exp((hlo ? l0.z : l0.w) + erB);
        accA.x += wA0 * fA0.x; accA.y += wA0 * fA0.y;
        accA.z += wA0 * fA0.z; accA.w += wA0 * fA0.w;
        accB.x += wB0 * fB0.x; accB.y += wB0 * fB0.y;
        accB.z += wB0 * fB0.z; accB.w += wB0 * fB0.w;
        wsumA += wA0; wsumB += wB0;
    }

    float invA = (deg > 0) ? (1.f / wsumA) : 0.f;
    float invB = (deg > 0) ? (1.f / wsumB) : 0.f;
    float4 bA = __ldg((const float4*)(bias + lane * 4));
    float4 bB = __ldg((const float4*)(bias + 128 + lane * 4));
    float4 oA, oB;
    oA.x = fmaxf(accA.x * invA + bA.x, 0.f);
    oA.y = fmaxf(accA.y * invA + bA.y, 0.f);
    oA.z = fmaxf(accA.z * invA + bA.z, 0.f);
    oA.w = fmaxf(accA.w * invA + bA.w, 0.f);
    oB.x = fmaxf(accB.x * invB + bB.x, 0.f);
    oB.y = fmaxf(accB.y * invB + bB.y, 0.f);
    oB.z = fmaxf(accB.z * invB + bB.z, 0.f);
    oB.w = fmaxf(accB.w * invB + bB.w, 0.f);

    uint32_t hA0, lA0, hA1, lA1, hB0, lB0, hB1, lB1;
    split2(make_float2(oA.x, oA.y), hA0, lA0);
    split2(make_float2(oA.z, oA.w), hA1, lA1);
    split2(make_float2(oB.x, oB.y), hB0, lB0);
    split2(make_float2(oB.z, oB.w), hB1, lB1);
    *(uint2*)(outh + (size_t)n * 256 + lane * 4)       = make_uint2(hA0, hA1);
    *(uint2*)(outl + (size_t)n * 256 + lane * 4)       = make_uint2(lA0, lA1);
    *(uint2*)(outh + (size_t)n * 256 + 128 + lane * 4) = make_uint2(hB0, hB1);
    *(uint2*)(outl + (size_t)n * 256 + 128 + lane * 4) = make_uint2(lB0, lB1);
}

// layer 2: H=1, D=128, fp32 features. Combined el/er arrays.
__global__ __launch_bounds__(256) void aggregate2_kernel(
    const float* __restrict__ ft, const float* __restrict__ el, const float* __restrict__ er,
    const int* __restrict__ rowptr, const int* __restrict__ colsrc,
    const float* __restrict__ bias, float* __restrict__ out, int Nn)
{
    int warp = threadIdx.x >> 5, lane = threadIdx.x & 31;
    int n = blockIdx.x * 8 + warp;
    if (n >= Nn) return;
    int start = rowptr[n];
    int deg = rowptr[n + 1] - start;

    float er_n = __ldg(&er[n]);
    float4 acc = make_float4(0.f, 0.f, 0.f, 0.f);
    float wsum = 0.f;
    const float* ftp = ft + lane * 4;

    int k = 0;
    for (; k + 8 <= deg; k += 8) {
        int s[8];
        #pragma unroll
        for (int u = 0; u < 8; u++) s[u] = __ldg(&colsrc[start + k + u]);
        float e[8];
        #pragma unroll
        for (int u = 0; u < 8; u++) e[u] = __ldg(&el[s[u]]);
        float4 f[8];
        #pragma unroll
        for (int u = 0; u < 8; u++) f[u] = *(const float4*)(ftp + (size_t)s[u] * 128);
        #pragma unroll
        for (int u = 0; u < 8; u++) {
            float w = leaky_exp(e[u] + er_n);
            acc.x += w * f[u].x; acc.y += w * f[u].y;
            acc.z += w * f[u].z; acc.w += w * f[u].w;
            wsum += w;
        }
    }
    for (; k < deg; k++) {
        int s0 = __ldg(&colsrc[start + k]);
        float w = leaky_exp(__ldg(&el[s0]) + er_n);
        float4 f0 = *(const float4*)(ftp + (size_t)s0 * 128);
        acc.x += w * f0.x; acc.y += w * f0.y;
        acc.z += w * f0.z; acc.w += w * f0.w;
        wsum += w;
    }

    float inv = (deg > 0) ? (1.f / wsum) : 0.f;
    float4 b = __ldg((const float4*)(bias + lane * 4));
    float4 o;
    o.x = acc.x * inv + b.x;
    o.y = acc.y * inv + b.y;
    o.z = acc.z * inv + b.z;
    o.w = acc.w * inv + b.w;
    *(float4*)(out + (size_t)n * 128 + lane * 4) = o;
}

// ---------------- launch (single stream) ----------------
extern "C" void kernel_launch(void* const* d_in, const int* in_sizes, int n_in,
                              void* d_out, int out_size)
{
    const float* feat    = (const float*)d_in[0];
    const int*   src     = (const int*)  d_in[1];
    const int*   dst     = (const int*)  d_in[2];
    const float* W1      = (const float*)d_in[3];
    const float* attn_l1 = (const float*)d_in[4];
    const float* attn_r1 = (const float*)d_in[5];
    const float* bias1   = (const float*)d_in[6];
    const float* W2      = (const float*)d_in[7];
    const float* attn_l2 = (const float*)d_in[8];
    const float* attn_r2 = (const float*)d_in[9];
    const float* bias2   = (const float*)d_in[10];
    float* out = (float*)d_out;

    float *ft1, *el1, *er1, *ft2, *el2, *er2;
    __half *h1h, *h1l, *wt1h, *wt2h;
    int *cnt, *rowptr, *colsrc, *bsum;
    cudaGetSymbolAddress((void**)&ft1,    g_ft1);
    cudaGetSymbolAddress((void**)&h1h,    g_h1h);
    cudaGetSymbolAddress((void**)&h1l,    g_h1l);
    cudaGetSymbolAddress((void**)&el1,    g_el1);
    cudaGetSymbolAddress((void**)&er1,    g_er1);
    cudaGetSymbolAddress((void**)&ft2,    g_ft2);
    cudaGetSymbolAddress((void**)&el2,    g_el2);
    cudaGetSymbolAddress((void**)&er2,    g_er2);
    cudaGetSymbolAddress((void**)&wt1h,   g_wt1h);
    cudaGetSymbolAddress((void**)&wt2h,   g_wt2h);
    cudaGetSymbolAddress((void**)&cnt,    g_cnt);
    cudaGetSymbolAddress((void**)&rowptr, g_rowptr);
    cudaGetSymbolAddress((void**)&colsrc, g_colsrc);
    cudaGetSymbolAddress((void**)&bsum,   g_bsum);

    const int SMEM_SZ  = (2 * 128 * 40) * 4 + (2 * 64 * 20) * 4;                 // 51200
    const int SMEM_SZA = (2 * 2 * 128 * 20) * 4 + (2 * 64 * 20) * 4;             // 51200
    cudaFuncSetAttribute(mma_gemm_f16_kernel,  cudaFuncAttributeMaxDynamicSharedMemorySize, SMEM_SZ);
    cudaFuncSetAttribute(mma_gemm_f16a_kernel, cudaFuncAttributeMaxDynamicSharedMemorySize, SMEM_SZA);

    transpose_split_kernel<<<384, 256>>>(W1, W2, wt1h, wt2h, cnt, el2, er2);       // 1
    count_dst_kernel<<<2048, 256>>>(dst, cnt, N_EDGES);                            // 2
    scan1_kernel<<<SCAN_NB, 1024>>>(cnt, rowptr, bsum, N_NODES);                   // 3
    {                                                                              // 4: gemm1 (profiled)
        dim3 grid(4, (N_NODES + 127) / 128);
        mma_gemm_f16_kernel<<<grid, 256, SMEM_SZ>>>(feat, wt1h, ft1,
                                                    attn_l1, attn_r1, el1, er1,
                                                    N_NODES, 256);
    }
    scan2_kernel<<<1, 64>>>(bsum, SCAN_NB);                                        // 5
    scan3_kernel<<<(N_NODES + 255) / 256, 256>>>(rowptr, bsum, N_NODES);           // 6
    scatter_kernel<<<2048, 256>>>(src, dst, rowptr, cnt, colsrc, N_EDGES);         // 7
    aggregate1_kernel<<<(N_NODES + 7) / 8, 256>>>(ft1, el1, er1, rowptr, colsrc,   // 8
                                                  bias1, h1h, h1l, N_NODES);
    {                                                                              // 9: gemm2 (fp16 A)
        dim3 grid(2, (N_NODES + 127) / 128);
        mma_gemm_f16a_kernel<<<grid, 256, SMEM_SZA>>>(h1h, h1l, wt2h, ft2,
                                                      attn_l2, attn_r2, el2, er2,
                                                      N_NODES, 128);
    }
    aggregate2_kernel<<<(N_NODES + 7) / 8, 256>>>(ft2, el2, er2, rowptr, colsrc,   // 10
                                                  bias2, out, N_NODES);
}

// round 16
// speedup vs baseline: 1.4047x; 1.0614x over previous
#include <cuda_runtime.h>
#include <cuda_fp16.h>
#include <math.h>
#include <stdint.h>

#define N_NODES 50000
#define N_EDGES 800000
#define NEG_SLOPE 0.2f
#define SCAN_NB ((N_NODES + 1023) / 1024)   // 49

// ---------------- scratch (device globals; no allocation allowed) ----------------
__device__ __half g_feath[N_NODES * 256];  // feat converted to fp16
__device__ float  g_ft1[N_NODES * 256];
__device__ __half g_h1h[N_NODES * 256];    // layer-1 output, fp16
__device__ float  g_el1[N_NODES * 4];
__device__ float  g_er1[N_NODES * 4];
__device__ float  g_ft2[N_NODES * 128];
__device__ float  g_el2[N_NODES];
__device__ float  g_er2[N_NODES];
__device__ int    g_cnt[N_NODES];
__device__ int    g_rowptr[N_NODES + 1];
__device__ int    g_bsum[64];
__device__ int    g_colsrc[N_EDGES];
__device__ __half g_wt1h[256 * 256];   // W1^T fp16 [n][k]
__device__ __half g_wt2h[128 * 256];   // W2^T fp16

// ---------------- helpers ----------------
__device__ __forceinline__ uint32_t smem_u32(const void* p) {
    uint32_t a;
    asm("{ .reg .u64 t; cvta.to.shared.u64 t, %1; cvt.u32.u64 %0, t; }" : "=r"(a) : "l"(p));
    return a;
}

#define CP_ASYNC16(sa, gp) \
    asm volatile("cp.async.cg.shared.global [%0], [%1], 16;" :: "r"(sa), "l"(gp) : "memory")
#define CP_ASYNC16_Z(sa, gp, sz) \
    asm volatile("cp.async.cg.shared.global [%0], [%1], 16, %2;" :: "r"(sa), "l"(gp), "r"(sz) : "memory")
#define CP_COMMIT()  asm volatile("cp.async.commit_group;" ::: "memory")
#define CP_WAIT(n)   asm volatile("cp.async.wait_group %0;" :: "n"(n) : "memory")

#define MMA_F16(d, a0, a1, a2, a3, b0, b1)                                    \
    asm volatile("mma.sync.aligned.m16n8k16.row.col.f32.f16.f16.f32 "         \
                 "{%0,%1,%2,%3}, {%4,%5,%6,%7}, {%8,%9}, {%0,%1,%2,%3};"      \
                 : "+f"(d[0]), "+f"(d[1]), "+f"(d[2]), "+f"(d[3])             \
                 : "r"(a0), "r"(a1), "r"(a2), "r"(a3), "r"(b0), "r"(b1))

#define LDSM_X4(r0, r1, r2, r3, addr)                                         \
    asm volatile("ldmatrix.sync.aligned.m8n8.x4.shared.b16 {%0,%1,%2,%3}, [%4];" \
                 : "=r"(r0), "=r"(r1), "=r"(r2), "=r"(r3) : "r"(addr))

// ---------------- small utils ----------------
__global__ void count_dst_kernel(const int* __restrict__ dst, int* __restrict__ cnt, int E) {
    for (int e = blockIdx.x * blockDim.x + threadIdx.x; e < E; e += gridDim.x * blockDim.x)
        atomicAdd(&cnt[dst[e]], 1);
}

// prep: transpose+fp16 W1/W2, convert feat->fp16, zero cnt/el2/er2
__global__ void prep_kernel(const float* __restrict__ feat,
                            const float* __restrict__ W1, const float* __restrict__ W2,
                            __half* __restrict__ feath,
                            __half* __restrict__ t1h, __half* __restrict__ t2h,
                            int* __restrict__ cnt,
                            float* __restrict__ el2, float* __restrict__ er2) {
    int t = blockIdx.x * blockDim.x + threadIdx.x;
    int nt = gridDim.x * blockDim.x;
    if (t < N_NODES) { cnt[t] = 0; el2[t] = 0.f; er2[t] = 0.f; }
    if (t < 65536) {
        int k = t & 255, n = t >> 8;
        t1h[n * 256 + k] = __float2half_rn(W1[k * 256 + n]);
    } else if (t < 98304) {
        int u = t - 65536;
        int k = u & 255, n = u >> 8;
        t2h[n * 256 + k] = __float2half_rn(W2[k * 128 + n]);
    }
    const float2* f2 = (const float2*)feat;
    __half2* fh2 = (__half2*)feath;
    for (int i = t; i < N_NODES * 128; i += nt)
        fh2[i] = __float22half2_rn(f2[i]);
}

// ---- parallel 3-phase scan ----
__global__ __launch_bounds__(1024) void scan1_kernel(const int* __restrict__ cnt,
                                                     int* __restrict__ rowptr,
                                                     int* __restrict__ bsum, int n) {
    __shared__ int warp_sums[32];
    int tid = threadIdx.x, lane = tid & 31, warp = tid >> 5;
    int idx = blockIdx.x * 1024 + tid;
    int v = (idx < n) ? cnt[idx] : 0;
    int x = v;
    #pragma unroll
    for (int off = 1; off < 32; off <<= 1) {
        int y = __shfl_up_sync(0xffffffffu, x, off);
        if (lane >= off) x += y;
    }
    if (lane == 31) warp_sums[warp] = x;
    __syncthreads();
    if (warp == 0) {
        int s = warp_sums[lane];
        #pragma unroll
        for (int off = 1; off < 32; off <<= 1) {
            int y = __shfl_up_sync(0xffffffffu, s, off);
            if (lane >= off) s += y;
        }
        warp_sums[lane] = s;
    }
    __syncthreads();
    int incl = x + ((warp > 0) ? warp_sums[warp - 1] : 0);
    if (idx < n) rowptr[idx + 1] = incl;
    if (tid == 1023) bsum[blockIdx.x] = incl;
}

__global__ void scan2_kernel(int* __restrict__ bsum, int nb) {
    __shared__ int s[64];
    int tid = threadIdx.x;
    s[tid] = (tid < nb) ? bsum[tid] : 0;
    __syncthreads();
    if (tid == 0) {
        int acc = 0;
        for (int i = 0; i < nb; i++) { int t = s[i]; s[i] = acc; acc += t; }
    }
    __syncthreads();
    if (tid < nb) bsum[tid] = s[tid];
}

__global__ void scan3_kernel(int* __restrict__ rowptr, const int* __restrict__ bsum, int n) {
    int idx = blockIdx.x * blockDim.x + threadIdx.x;
    if (idx == 0) rowptr[0] = 0;
    if (idx < n) rowptr[idx + 1] += bsum[idx >> 10];
}

__global__ void scatter_kernel(const int* __restrict__ src, const int* __restrict__ dst,
                               const int* __restrict__ rowptr, int* __restrict__ cnt,
                               int* __restrict__ colsrc, int E) {
    for (int e = blockIdx.x * blockDim.x + threadIdx.x; e < E; e += gridDim.x * blockDim.x) {
        int d = dst[e];
        int pos = atomicSub(&cnt[d], 1);
        colsrc[rowptr[d] + pos - 1] = src[e];
    }
}

// ---------------- pure fp16 MMA GEMM (A fp16, B fp16, fp32 accum) + fused el/er ----------------
// Both operands via ldmatrix.x4; 1 MMA per fragment pair.
// HEADS=4: el/er direct store per head=blockIdx.x. HEADS=1: atomicAdd into combined arrays.
template <int HEADS>
__global__ __launch_bounds__(256, 3) void mma_gemm_pf16_kernel(
    const __half* __restrict__ Ath, const __half* __restrict__ Bth,
    float* __restrict__ C,
    const float* __restrict__ attn_l, const float* __restrict__ attn_r,
    float* __restrict__ el, float* __restrict__ er,
    int M, int Nc)
{
    const int BM = 128, BN = 64, BK = 32, K = 256;
    const int STR2 = 20;   // half2 per row (16 data + 4 pad)
    extern __shared__ float sm[];
    __half2* Ah2 = (__half2*)sm;                  // [2][BM][20]
    __half2* Bh2 = Ah2 + 2 * BM * STR2;           // [2][BN][20]

    uint32_t ah_b = smem_u32(Ah2);
    uint32_t bh_b = smem_u32(Bh2);

    int tid = threadIdx.x, lane = tid & 31, warp = tid >> 5;
    int blockRow = blockIdx.y * BM;
    int blockCol = blockIdx.x * BN;
    int g = lane >> 2, q = lane & 3;
    int lm = lane >> 3, lr = lane & 7;
    // A x4: m0=(rows+0,klo) m1=(rows+8,klo) m2=(rows+0,khi) m3=(rows+8,khi)
    uint32_t a_lane_off = (uint32_t)((((lm & 1) * 8 + lr) * 80) + (lm >> 1) * 16);
    // B x4: m0=(j0,klo) m1=(j0,khi) m2=(j1,klo) m3=(j1,khi)
    uint32_t b_lane_off = (uint32_t)((((lm >> 1) * 8 + lr) * 80) + (lm & 1) * 16);

    float acc[8][4];
    #pragma unroll
    for (int j = 0; j < 8; j++)
        #pragma unroll
        for (int c = 0; c < 4; c++) acc[j][c] = 0.f;

    auto load_tile = [&](int t) {
        int buf = t & 1, k0 = t * BK;
        // A: 128 rows x 32 halves = 4 chunks/row -> 512 chunks, 2 per thread
        #pragma unroll
        for (int l = 0; l < 2; l++) {
            int c = tid + l * 256;
            int r = c >> 2, ch = c & 3;
            size_t go = (size_t)(blockRow + r) * K + k0 + ch * 8;
            uint32_t so = (uint32_t)(((buf * BM + r) * STR2 + ch * 4) * 4);
            uint32_t sz = (blockRow + r < M) ? 16u : 0u;
            CP_ASYNC16_Z(ah_b + so, Ath + go, sz);
        }
        // B: 64 rows x 32 halves -> 256 chunks, 1 per thread
        {
            int n = tid >> 2, ch = tid & 3;
            size_t go = (size_t)(blockCol + n) * K + k0 + ch * 8;
            uint32_t so = (uint32_t)(((buf * BN + n) * STR2 + ch * 4) * 4);
            CP_ASYNC16(bh_b + so, Bth + go);
        }
        CP_COMMIT();
    };

    load_tile(0);

    #pragma unroll 1
    for (int t = 0; t < K / BK; t++) {
        if (t < K / BK - 1) {
            load_tile(t + 1);
            CP_WAIT(1);
        } else {
            CP_WAIT(0);
        }
        __syncthreads();

        int buf = t & 1;
        uint32_t ah_buf = ah_b + (uint32_t)(buf * 10240 + warp * 1280) + a_lane_off;
        uint32_t bh_buf = bh_b + (uint32_t)(buf * 5120) + b_lane_off;

        #pragma unroll
        for (int ks = 0; ks < 2; ks++) {
            uint32_t koff = (uint32_t)(ks * 32);
            uint32_t ah[4];
            LDSM_X4(ah[0], ah[1], ah[2], ah[3], ah_buf + koff);
            #pragma unroll
            for (int p = 0; p < 4; p++) {
                uint32_t bh0, bh1, bh2_, bh3;
                LDSM_X4(bh0, bh1, bh2_, bh3, bh_buf + (uint32_t)(p * 1280) + koff);
                MMA_F16(acc[2 * p],     ah[0], ah[1], ah[2], ah[3], bh0, bh1);
                MMA_F16(acc[2 * p + 1], ah[0], ah[1], ah[2], ah[3], bh2_, bh3);
            }
        }
        __syncthreads();
    }

    // ---- store C (fp32) ----
    int r0 = blockRow + warp * 16 + g;
    int r1 = r0 + 8;
    #pragma unroll
    for (int j = 0; j < 8; j++) {
        int c = blockCol + j * 8 + q * 2;
        if (r0 < M) *(float2*)(C + (size_t)r0 * Nc + c) = make_float2(acc[j][0], acc[j][1]);
        if (r1 < M) *(float2*)(C + (size_t)r1 * Nc + c) = make_float2(acc[j][2], acc[j][3]);
    }

    // ---- fused el/er epilogue ----
    float pl0 = 0.f, pl1 = 0.f, pr0 = 0.f, pr1 = 0.f;
    #pragma unroll
    for (int j = 0; j < 8; j++) {
        int idx = blockCol + j * 8 + q * 2;
        float a0 = __ldg(&attn_l[idx]), a1 = __ldg(&attn_l[idx + 1]);
        float b0 = __ldg(&attn_r[idx]), b1 = __ldg(&attn_r[idx + 1]);
        pl0 += acc[j][0] * a0 + acc[j][1] * a1;
        pl1 += acc[j][2] * a0 + acc[j][3] * a1;
        pr0 += acc[j][0] * b0 + acc[j][1] * b1;
        pr1 += acc[j][2] * b0 + acc[j][3] * b1;
    }
    #pragma unroll
    for (int off = 1; off <= 2; off <<= 1) {
        pl0 += __shfl_xor_sync(0xffffffffu, pl0, off);
        pl1 += __shfl_xor_sync(0xffffffffu, pl1, off);
        pr0 += __shfl_xor_sync(0xffffffffu, pr0, off);
        pr1 += __shfl_xor_sync(0xffffffffu, pr1, off);
    }
    if (q == 0) {
        if (HEADS == 4) {
            if (r0 < M) {
                el[(size_t)r0 * 4 + blockIdx.x] = pl0;
                er[(size_t)r0 * 4 + blockIdx.x] = pr0;
            }
            if (r1 < M) {
                el[(size_t)r1 * 4 + blockIdx.x] = pl1;
                er[(size_t)r1 * 4 + blockIdx.x] = pr1;
            }
        } else {
            if (r0 < M) { atomicAdd(&el[r0], pl0); atomicAdd(&er[r0], pr0); }
            if (r1 < M) { atomicAdd(&el[r1], pl1); atomicAdd(&er[r1], pr1); }
        }
    }
}

// ---------------- fused softmax + aggregation ----------------
__device__ __forceinline__ float leaky_exp(float e) {
    e = (e > 0.f) ? e : NEG_SLOPE * e;
    return __expf(e);
}

// layer 1: H=4, D=64, C=256, fp32 features. One warp per node. Output h1 as fp16.
__global__ __launch_bounds__(256) void aggregate1_kernel(
    const float* __restrict__ ft, const float* __restrict__ el, const float* __restrict__ er,
    const int* __restrict__ rowptr, const int* __restrict__ colsrc,
    const float* __restrict__ bias, __half* __restrict__ outh, int Nn)
{
    int warp = threadIdx.x >> 5, lane = threadIdx.x & 31;
    int n = blockIdx.x * 8 + warp;
    if (n >= Nn) return;
    int start = rowptr[n];
    int deg = rowptr[n + 1] - start;

    const bool hlo = (lane < 16);
    float4 er4 = __ldg((const float4*)(er + (size_t)n * 4));
    float erA = hlo ? er4.x : er4.y;
    float erB = hlo ? er4.z : er4.w;

    float4 accA = make_float4(0.f, 0.f, 0.f, 0.f);
    float4 accB = make_float4(0.f, 0.f, 0.f, 0.f);
    float wsumA = 0.f, wsumB = 0.f;
    const float* ftA = ft + lane * 4;
    const float* ftB = ft + 128 + lane * 4;

    int k = 0;
    for (; k + 4 <= deg; k += 4) {
        int s0 = __ldg(&colsrc[start + k + 0]);
        int s1 = __ldg(&colsrc[start + k + 1]);
        int s2 = __ldg(&colsrc[start + k + 2]);
        int s3 = __ldg(&colsrc[start + k + 3]);
        float4 l0 = __ldg((const float4*)(el + (size_t)s0 * 4));
        float4 l1 = __ldg((const float4*)(el + (size_t)s1 * 4));
        float4 l2 = __ldg((const float4*)(el + (size_t)s2 * 4));
        float4 l3 = __ldg((const float4*)(el + (size_t)s3 * 4));
        float4 fA0 = *(const float4*)(ftA + (size_t)s0 * 256);
        float4 fB0 = *(const float4*)(ftB + (size_t)s0 * 256);
        float4 fA1 = *(const float4*)(ftA + (size_t)s1 * 256);
        float4 fB1 = *(const float4*)(ftB + (size_t)s1 * 256);
        float4 fA2 = *(const float4*)(ftA + (size_t)s2 * 256);
        float4 fB2 = *(const float4*)(ftB + (size_t)s2 * 256);
        float4 fA3 = *(const float4*)(ftA + (size_t)s3 * 256);
        float4 fB3 = *(const float4*)(ftB + (size_t)s3 * 256);
        float wA0 = leaky_exp((hlo ? l0.x : l0.y) + erA);
        float wB0 = leaky_exp((hlo ? l0.z : l0.w) + erB);
        float wA1 = leaky_exp((hlo ? l1.x : l1.y) + erA);
        float wB1 = leaky_exp((hlo ? l1.z : l1.w) + erB);
        float wA2 = leaky_exp((hlo ? l2.x : l2.y) + erA);
        float wB2 = leaky_exp((hlo ? l2.z : l2.w) + erB);
        float wA3 = leaky_exp((hlo ? l3.x : l3.y) + erA);
        float wB3 = leaky_exp((hlo ? l3.z : l3.w) + erB);
        accA.x += wA0 * fA0.x + wA1 * fA1.x + wA2 * fA2.x + wA3 * fA3.x;
        accA.y += wA0 * fA0.y + wA1 * fA1.y + wA2 * fA2.y + wA3 * fA3.y;
        accA.z += wA0 * fA0.z + wA1 * fA1.z + wA2 * fA2.z + wA3 * fA3.z;
        accA.w += wA0 * fA0.w + wA1 * fA1.w + wA2 * fA2.w + wA3 * fA3.w;
        accB.x += wB0 * fB0.x + wB1 * fB1.x + wB2 * fB2.x + wB3 * fB3.x;
        accB.y += wB0 * fB0.y + wB1 * fB1.y + wB2 * fB2.y + wB3 * fB3.y;
        accB.z += wB0 * fB0.z + wB1 * fB1.z + wB2 * fB2.z + wB3 * fB3.z;
        accB.w += wB0 * fB0.w + wB1 * fB1.w + wB2 * fB2.w + wB3 * fB3.w;
        wsumA += (wA0 + wA1) + (wA2 + wA3);
        wsumB += (wB0 + wB1) + (wB2 + wB3);
    }
    for (; k < deg; k++) {
        int s0 = __ldg(&colsrc[start + k]);
        float4 l0 = __ldg((const float4*)(el + (size_t)s0 * 4));
        float4 fA0 = *(const float4*)(ftA + (size_t)s0 * 256);
        float4 fB0 = *(const float4*)(ftB + (size_t)s0 * 256);
        float wA0 = leaky_exp((hlo ? l0.x : l0.y) + erA);
        float wB0 = leaky_exp((hlo ? l0.z : l0.w) + erB);
        accA.x += wA0 * fA0.x; accA.y += wA0 * fA0.y;
        accA.z += wA0 * fA0.z; accA.w += wA0 * fA0.w;
        accB.x += wB0 * fB0.x; accB.y += wB0 * fB0.y;
        accB.z += wB0 * fB0.z; accB.w += wB0 * fB0.w;
        wsumA += wA0; wsumB += wB0;
    }

    float invA = (deg > 0) ? (1.f / wsumA) : 0.f;
    float invB = (deg > 0) ? (1.f / wsumB) : 0.f;
    float4 bA = __ldg((const float4*)(bias + lane * 4));
    float4 bB = __ldg((const float4*)(bias + 128 + lane * 4));
    float4 oA, oB;
    oA.x = fmaxf(accA.x * invA + bA.x, 0.f);
    oA.y = fmaxf(accA.y * invA + bA.y, 0.f);
    oA.z = fmaxf(accA.z * invA + bA.z, 0.f);
    oA.w = fmaxf(accA.w * invA + bA.w, 0.f);
    oB.x = fmaxf(accB.x * invB + bB.x, 0.f);
    oB.y = fmaxf(accB.y * invB + bB.y, 0.f);
    oB.z = fmaxf(accB.z * invB + bB.z, 0.f);
    oB.w = fmaxf(accB.w * invB + bB.w, 0.f);

    __half2 hA0 = __floats2half2_rn(oA.x, oA.y);
    __half2 hA1 = __floats2half2_rn(oA.z, oA.w);
    __half2 hB0 = __floats2half2_rn(oB.x, oB.y);
    __half2 hB1 = __floats2half2_rn(oB.z, oB.w);
    *(uint2*)(outh + (size_t)n * 256 + lane * 4) =
        make_uint2(*(uint32_t*)&hA0, *(uint32_t*)&hA1);
    *(uint2*)(outh + (size_t)n * 256 + 128 + lane * 4) =
        make_uint2(*(uint32_t*)&hB0, *(uint32_t*)&hB1);
}

// layer 2: H=1, D=128, fp32 features. Combined el/er arrays.
__global__ __launch_bounds__(256) void aggregate2_kernel(
    const float* __restrict__ ft, const float* __restrict__ el, const float* __restrict__ er,
    const int* __restrict__ rowptr, const int* __restrict__ colsrc,
    const float* __restrict__ bias, float* __restrict__ out, int Nn)
{
    int warp = threadIdx.x >> 5, lane = threadIdx.x & 31;
    int n = blockIdx.x * 8 + warp;
    if (n >= Nn) return;
    int start = rowptr[n];
    int deg = rowptr[n + 1] - start;

    float er_n = __ldg(&er[n]);
    float4 acc = make_float4(0.f, 0.f, 0.f, 0.f);
    float wsum = 0.f;
    const float* ftp = ft + lane * 4;

    int k = 0;
    for (; k + 8 <= deg; k += 8) {
        int s[8];
        #pragma unroll
        for (int u = 0; u < 8; u++) s[u] = __ldg(&colsrc[start + k + u]);
        float e[8];
        #pragma unroll
        for (int u = 0; u < 8; u++) e[u] = __ldg(&el[s[u]]);
        float4 f[8];
        #pragma unroll
        for (int u = 0; u < 8; u++) f[u] = *(const float4*)(ftp + (size_t)s[u] * 128);
        #pragma unroll
        for (int u = 0; u < 8; u++) {
            float w = leaky_exp(e[u] + er_n);
            acc.x += w * f[u].x; acc.y += w * f[u].y;
            acc.z += w * f[u].z; acc.w += w * f[u].w;
            wsum += w;
        }
    }
    for (; k < deg; k++) {
        int s0 = __ldg(&colsrc[start + k]);
        float w = leaky_exp(__ldg(&el[s0]) + er_n);
        float4 f0 = *(const float4*)(ftp + (size_t)s0 * 128);
        acc.x += w * f0.x; acc.y += w * f0.y;
        acc.z += w * f0.z; acc.w += w * f0.w;
        wsum += w;
    }

    float inv = (deg > 0) ? (1.f / wsum) : 0.f;
    float4 b = __ldg((const float4*)(bias + lane * 4));
    float4 o;
    o.x = acc.x * inv + b.x;
    o.y = acc.y * inv + b.y;
    o.z = acc.z * inv + b.z;
    o.w = acc.w * inv + b.w;
    *(float4*)(out + (size_t)n * 128 + lane * 4) = o;
}

// ---------------- launch (single stream) ----------------
extern "C" void kernel_launch(void* const* d_in, const int* in_sizes, int n_in,
                              void* d_out, int out_size)
{
    const float* feat    = (const float*)d_in[0];
    const int*   src     = (const int*)  d_in[1];
    const int*   dst     = (const int*)  d_in[2];
    const float* W1      = (const float*)d_in[3];
    const float* attn_l1 = (const float*)d_in[4];
    const float* attn_r1 = (const float*)d_in[5];
    const float* bias1   = (const float*)d_in[6];
    const float* W2      = (const float*)d_in[7];
    const float* attn_l2 = (const float*)d_in[8];
    const float* attn_r2 = (const float*)d_in[9];
    const float* bias2   = (const float*)d_in[10];
    float* out = (float*)d_out;

    float *ft1, *el1, *er1, *ft2, *el2, *er2;
    __half *feath, *h1h, *wt1h, *wt2h;
    int *cnt, *rowptr, *colsrc, *bsum;
    cudaGetSymbolAddress((void**)&feath,  g_feath);
    cudaGetSymbolAddress((void**)&ft1,    g_ft1);
    cudaGetSymbolAddress((void**)&h1h,    g_h1h);
    cudaGetSymbolAddress((void**)&el1,    g_el1);
    cudaGetSymbolAddress((void**)&er1,    g_er1);
    cudaGetSymbolAddress((void**)&ft2,    g_ft2);
    cudaGetSymbolAddress((void**)&el2,    g_el2);
    cudaGetSymbolAddress((void**)&er2,    g_er2);
    cudaGetSymbolAddress((void**)&wt1h,   g_wt1h);
    cudaGetSymbolAddress((void**)&wt2h,   g_wt2h);
    cudaGetSymbolAddress((void**)&cnt,    g_cnt);
    cudaGetSymbolAddress((void**)&rowptr, g_rowptr);
    cudaGetSymbolAddress((void**)&colsrc, g_colsrc);
    cudaGetSymbolAddress((void**)&bsum,   g_bsum);

    const int SMEM_SZ = (2 * 128 * 20 + 2 * 64 * 20) * 4;   // 30720
    cudaFuncSetAttribute(mma_gemm_pf16_kernel<4>, cudaFuncAttributeMaxDynamicSharedMemorySize, SMEM_SZ);
    cudaFuncSetAttribute(mma_gemm_pf16_kernel<1>, cudaFuncAttributeMaxDynamicSharedMemorySize, SMEM_SZ);

    prep_kernel<<<2048, 256>>>(feat, W1, W2, feath, wt1h, wt2h, cnt, el2, er2);    // 1
    count_dst_kernel<<<2048, 256>>>(dst, cnt, N_EDGES);                            // 2
    scan1_kernel<<<SCAN_NB, 1024>>>(cnt, rowptr, bsum, N_NODES);                   // 3
    {                                                                              // 4: gemm1 (profiled)
        dim3 grid(4, (N_NODES + 127) / 128);
        mma_gemm_pf16_kernel<4><<<grid, 256, SMEM_SZ>>>(feath, wt1h, ft1,
                                                        attn_l1, attn_r1, el1, er1,
                                                        N_NODES, 256);
    }
    scan2_kernel<<<1, 64>>>(bsum, SCAN_NB);                                        // 5
    scan3_kernel<<<(N_NODES + 255) / 256, 256>>>(rowptr, bsum, N_NODES);           // 6
    scatter_kernel<<<2048, 256>>>(src, dst, rowptr, cnt, colsrc, N_EDGES);         // 7
    aggregate1_kernel<<<(N_NODES + 7) / 8, 256>>>(ft1, el1, er1, rowptr, colsrc,   // 8
                                                  bias1, h1h, N_NODES);
    {                                                                              // 9: gemm2
        dim3 grid(2, (N_NODES + 127) / 128);
        mma_gemm_pf16_kernel<1><<<grid, 256, SMEM_SZ>>>(h1h, wt2h, ft2,
                                                        attn_l2, attn_r2, el2, er2,
                                                        N_NODES, 128);
    }
    aggregate2_kernel<<<(N_NODES + 7) / 8, 256>>>(ft2, el2, er2, rowptr, colsrc,   // 10
                                                  bias2, out, N_NODES);
}